// round 14
// baseline (speedup 1.0000x reference)
#include <cuda_runtime.h>
#include <cuda_fp16.h>
#include <math.h>

#define BB 256
#define NN 196
#define CC 784
#define HH 4
#define DD 196
#define MM (BB*NN)          // 50176 tokens
#define PSTR 216            // padded col stride (halves) for attn operands
#define PROWS 256           // padded rows per (b,h)
#define NBH (BB*HH)

// ---------------- scratch (device globals; pads rely on zero-init) ----------
__device__ __align__(16) float  g_L[(size_t)NBH * NN * NN];
__device__ __align__(16) __half g_Xh[(size_t)MM * CC];
__device__ __align__(16) __half g_Xl[(size_t)MM * CC];
__device__ __align__(16) __half g_Oh[(size_t)MM * CC];
__device__ __align__(16) __half g_Wqh[CC * CC];
__device__ __align__(16) __half g_Wql[CC * CC];
__device__ __align__(16) __half g_Wkh[CC * CC];
__device__ __align__(16) __half g_Wvh[CC * CC];
__device__ __align__(16) __half g_Woh[CC * CC];
// attention operands, padded [bh][PROWS][PSTR]; pads stay zero forever
__device__ __align__(16) __half g_qh [(size_t)NBH * PROWS * PSTR];
__device__ __align__(16) __half g_ql [(size_t)NBH * PROWS * PSTR];
__device__ __align__(16) __half g_qth[(size_t)NBH * PROWS * PSTR];
__device__ __align__(16) __half g_qtl[(size_t)NBH * PROWS * PSTR];
__device__ __align__(16) __half g_kh [(size_t)NBH * PROWS * PSTR];
__device__ __align__(16) __half g_vth[(size_t)NBH * PROWS * PSTR];
__device__ __align__(16) __half g_ph [(size_t)NBH * PROWS * PSTR];
__device__ __align__(16) __half g_cph[HH * PROWS * PSTR];
__device__ __align__(16) __half g_cpl[HH * PROWS * PSTR];

// ---------------- helpers ----------------------------------------------------
__device__ __forceinline__ void mma16816(float* c, const unsigned* a, const unsigned* b) {
    asm("mma.sync.aligned.m16n8k16.row.col.f32.f16.f16.f32 "
        "{%0,%1,%2,%3}, {%4,%5,%6,%7}, {%8,%9}, {%0,%1,%2,%3};"
        : "+f"(c[0]), "+f"(c[1]), "+f"(c[2]), "+f"(c[3])
        : "r"(a[0]), "r"(a[1]), "r"(a[2]), "r"(a[3]), "r"(b[0]), "r"(b[1]));
}
__device__ __forceinline__ void ldsm_x4(unsigned* d, const __half* p) {
    unsigned s = (unsigned)__cvta_generic_to_shared(p);
    asm volatile("ldmatrix.sync.aligned.m8n8.x4.shared.b16 {%0,%1,%2,%3}, [%4];"
                 : "=r"(d[0]), "=r"(d[1]), "=r"(d[2]), "=r"(d[3]) : "r"(s));
}
__device__ __forceinline__ void ldsm_x2(unsigned* d, const __half* p) {
    unsigned s = (unsigned)__cvta_generic_to_shared(p);
    asm volatile("ldmatrix.sync.aligned.m8n8.x2.shared.b16 {%0,%1}, [%2];"
                 : "=r"(d[0]), "=r"(d[1]) : "r"(s));
}
#define CPA16(s, g) asm volatile("cp.async.cg.shared.global [%0], [%1], 16;" \
    :: "r"((unsigned)__cvta_generic_to_shared(s)), "l"(g))
#define CPA_COMMIT() asm volatile("cp.async.commit_group;")
#define CPA_WAIT3()  asm volatile("cp.async.wait_group 3;")

// ---------------- conversions ------------------------------------------------
__global__ void f2h_split_kernel(const float* __restrict__ in,
                                 __half* __restrict__ hi,
                                 __half* __restrict__ lo, int n) {
    int i = blockIdx.x * blockDim.x + threadIdx.x;
    if (i >= n) return;
    float f = in[i];
    __half h = __float2half_rn(f);
    hi[i] = h;
    lo[i] = __float2half_rn(f - __half2float(h));
}

// all four weights in one launch: Wq -> hi/lo, Wk/Wv/Wo -> hi only
__global__ void wconv_kernel(const float* __restrict__ Wq,
                             const float* __restrict__ Wk,
                             const float* __restrict__ Wv,
                             const float* __restrict__ Wo) {
    const int wn = CC * CC;
    int i = blockIdx.x * blockDim.x + threadIdx.x;
    if (i >= 4 * wn) return;
    int w = i / wn, j = i - w * wn;
    if (w == 0) {
        float f = Wq[j];
        __half h = __float2half_rn(f);
        g_Wqh[j] = h;
        g_Wql[j] = __float2half_rn(f - __half2float(h));
    } else if (w == 1) {
        g_Wkh[j] = __float2half_rn(Wk[j]);
    } else if (w == 2) {
        g_Wvh[j] = __float2half_rn(Wv[j]);
    } else {
        g_Woh[j] = __float2half_rn(Wo[j]);
    }
}

// cp[h][p][k] = rel_h[h,k,p/14] + rel_w[h,k,p%14], split hi/lo, padded
__global__ void cp_split_kernel(const float* __restrict__ rel_h,
                                const float* __restrict__ rel_w) {
    int idx = blockIdx.x * blockDim.x + threadIdx.x;
    if (idx >= HH * NN * DD) return;
    int h   = idx / (NN * DD);
    int rem = idx - h * (NN * DD);
    int p   = rem / DD;
    int k   = rem - p * DD;
    float v = rel_h[(h * DD + k) * 14 + (p / 14)]
            + rel_w[(h * DD + k) * 14 + (p % 14)];
    __half hi = __float2half_rn(v);
    size_t o = ((size_t)h * PROWS + p) * PSTR + k;
    g_cph[o] = hi;
    g_cpl[o] = __float2half_rn(v - __half2float(hi));
}

#define AST2 24
#define NSTAGE 4
#define KITERS 49

// ============ 3-term split-fp16 HMMA GEMM: Q projection ======================
// CTA 128 thr = 4 warps, warp tile 64x56. A-frag loads PHASED (afh used by
// hh+hl, then afl overwrites for lh) to keep regs < 255 (no spill).
#define STG3 ((128 + 128 + 112 + 112) * AST2)

__global__ __launch_bounds__(128) void hgemm_proj3(
    const __half* __restrict__ Ah, const __half* __restrict__ Al,
    const __half* __restrict__ Wh, const __half* __restrict__ Wl,
    const float* __restrict__ bias)
{
    extern __shared__ __half sm[];
    const int t    = threadIdx.x;
    const int lane = t & 31;
    const int wid  = t >> 5;        // 0..3
    const int wm   = wid & 1;       // m-group (64 rows)
    const int wn   = wid >> 1;      // n-group (56 cols)
    const int m0   = blockIdx.y * 128;
    const int n0   = blockIdx.x * 112;

    float acc[4][7][4];
#pragma unroll
    for (int i = 0; i < 4; i++)
#pragma unroll
        for (int j = 0; j < 7; j++)
#pragma unroll
            for (int r = 0; r < 4; r++) acc[i][j][r] = 0.f;

    auto prefetch = [&](int kt) {
        const int k0 = kt * 16;
        __half* st = sm + (kt & (NSTAGE - 1)) * STG3;
        for (int v = t; v < 960; v += 128) {
            const __half* g; __half* s;
            if (v < 512) {
                int part = v >> 8, rem = v & 255;
                int row = rem >> 1, ch = rem & 1;
                g = (part ? Al : Ah) + (size_t)(m0 + row) * CC + k0 + ch * 8;
                s = st + part * (128 * AST2) + row * AST2 + ch * 8;
            } else {
                int v2 = v - 512;
                int part = v2 / 224, rem = v2 % 224;
                int row = rem >> 1, ch = rem & 1;
                g = (part ? Wl : Wh) + (size_t)(n0 + row) * CC + k0 + ch * 8;
                s = st + 256 * AST2 + part * (112 * AST2) + row * AST2 + ch * 8;
            }
            CPA16(s, g);
        }
        CPA_COMMIT();
    };

    prefetch(0); prefetch(1); prefetch(2);

    for (int kt = 0; kt < KITERS; kt++) {
        if (kt + 3 < KITERS) prefetch(kt + 3);
        else CPA_COMMIT();
        CPA_WAIT3();
        __syncthreads();

        __half* st  = sm + (kt & (NSTAGE - 1)) * STG3;
        __half* Ash = st;
        __half* Asl = st + 128 * AST2;
        __half* Bsh = st + 256 * AST2;
        __half* Bsl = st + 256 * AST2 + 112 * AST2;

        // B fragments (hi + lo) stay live all k-step
        unsigned bfh[7][2], bfl[7][2];
#pragma unroll
        for (int p = 0; p < 3; p++) {
            int brow = wn * 56 + p * 16 + (lane & 7) + ((lane & 16) >> 1);
            int bcol = lane & 8;
            ldsm_x4(&bfh[2 * p][0], Bsh + brow * AST2 + bcol);
            ldsm_x4(&bfl[2 * p][0], Bsl + brow * AST2 + bcol);
        }
        {
            int brow = wn * 56 + 48 + (lane & 7);
            int bcol = lane & 8;
            ldsm_x2(bfh[6], Bsh + brow * AST2 + bcol);
            ldsm_x2(bfl[6], Bsl + brow * AST2 + bcol);
        }

        // phase 1+2: afh -> hh then hl terms
        {
            unsigned af[4][4];
#pragma unroll
            for (int mt = 0; mt < 4; mt++) {
                int arow = wm * 64 + mt * 16 + (lane & 15);
                int acol = (lane >> 4) << 3;
                ldsm_x4(af[mt], Ash + arow * AST2 + acol);
            }
#pragma unroll
            for (int mt = 0; mt < 4; mt++)
#pragma unroll
                for (int nt = 0; nt < 7; nt++)
                    mma16816(acc[mt][nt], af[mt], bfh[nt]);
#pragma unroll
            for (int mt = 0; mt < 4; mt++)
#pragma unroll
                for (int nt = 0; nt < 7; nt++)
                    mma16816(acc[mt][nt], af[mt], bfl[nt]);
        }
        // phase 3: afl -> lh term (reuses af register range)
        {
            unsigned af[4][4];
#pragma unroll
            for (int mt = 0; mt < 4; mt++) {
                int arow = wm * 64 + mt * 16 + (lane & 15);
                int acol = (lane >> 4) << 3;
                ldsm_x4(af[mt], Asl + arow * AST2 + acol);
            }
#pragma unroll
            for (int mt = 0; mt < 4; mt++)
#pragma unroll
                for (int nt = 0; nt < 7; nt++)
                    mma16816(acc[mt][nt], af[mt], bfh[nt]);
        }
        __syncthreads();
    }

    // epilogue: split to hi/lo, write q + q^T padded attention layouts
    auto put = [&](int row, int col, float f) {
        int b = row / NN, n = row - b * NN;
        int h = col / DD, d = col - h * DD;
        size_t bh = (size_t)b * HH + h;
        size_t o1 = (bh * PROWS + n) * PSTR + d;
        size_t o2 = (bh * PROWS + d) * PSTR + n;
        __half hi = __float2half_rn(f);
        __half lo = __float2half_rn(f - __half2float(hi));
        g_qh[o1]  = hi; g_ql[o1]  = lo;
        g_qth[o2] = hi; g_qtl[o2] = lo;
    };
#pragma unroll
    for (int mt = 0; mt < 4; mt++)
#pragma unroll
        for (int nt = 0; nt < 7; nt++) {
            int row = m0 + wm * 64 + mt * 16 + (lane >> 2);
            int col = n0 + wn * 56 + nt * 8 + (lane & 3) * 2;
            float b0 = bias[col], b1 = bias[col + 1];
            put(row,     col,     acc[mt][nt][0] + b0);
            put(row,     col + 1, acc[mt][nt][1] + b1);
            put(row + 8, col,     acc[mt][nt][2] + b0);
            put(row + 8, col + 1, acc[mt][nt][3] + b1);
        }
}

// ============ 1-term fp16 HMMA GEMM: K / V / O projections ==================
// MODE 0: K -> g_kh[bh][n][d];  MODE 1: V -> g_vth[bh][d][n];  MODE 2: fp32 Y
// CTA 128 thr, warp tile 64x56.
#define STG1 ((128 + 112) * AST2)

template<int MODE>
__global__ __launch_bounds__(128) void hgemm_proj1(
    const __half* __restrict__ Ah, const __half* __restrict__ Wh,
    const float* __restrict__ bias, float* __restrict__ Y)
{
    extern __shared__ __half sm[];
    const int t    = threadIdx.x;
    const int lane = t & 31;
    const int wid  = t >> 5;
    const int wm   = wid & 1;
    const int wn   = wid >> 1;
    const int m0   = blockIdx.y * 128;
    const int n0   = blockIdx.x * 112;

    float acc[4][7][4];
#pragma unroll
    for (int i = 0; i < 4; i++)
#pragma unroll
        for (int j = 0; j < 7; j++)
#pragma unroll
            for (int r = 0; r < 4; r++) acc[i][j][r] = 0.f;

    auto prefetch = [&](int kt) {
        const int k0 = kt * 16;
        __half* st = sm + (kt & (NSTAGE - 1)) * STG1;
        for (int v = t; v < 480; v += 128) {
            const __half* g; __half* s;
            if (v < 256) {
                int row = v >> 1, ch = v & 1;
                g = Ah + (size_t)(m0 + row) * CC + k0 + ch * 8;
                s = st + row * AST2 + ch * 8;
            } else {
                int v2 = v - 256;
                int row = v2 >> 1, ch = v2 & 1;
                g = Wh + (size_t)(n0 + row) * CC + k0 + ch * 8;
                s = st + 128 * AST2 + row * AST2 + ch * 8;
            }
            CPA16(s, g);
        }
        CPA_COMMIT();
    };

    prefetch(0); prefetch(1); prefetch(2);

    for (int kt = 0; kt < KITERS; kt++) {
        if (kt + 3 < KITERS) prefetch(kt + 3);
        else CPA_COMMIT();
        CPA_WAIT3();
        __syncthreads();

        __half* st  = sm + (kt & (NSTAGE - 1)) * STG1;
        __half* Ash = st;
        __half* Bsh = st + 128 * AST2;

        unsigned afh[4][4];
#pragma unroll
        for (int mt = 0; mt < 4; mt++) {
            int arow = wm * 64 + mt * 16 + (lane & 15);
            int acol = (lane >> 4) << 3;
            ldsm_x4(afh[mt], Ash + arow * AST2 + acol);
        }
        unsigned bfh[7][2];
#pragma unroll
        for (int p = 0; p < 3; p++) {
            int brow = wn * 56 + p * 16 + (lane & 7) + ((lane & 16) >> 1);
            int bcol = lane & 8;
            ldsm_x4(&bfh[2 * p][0], Bsh + brow * AST2 + bcol);
        }
        {
            int brow = wn * 56 + 48 + (lane & 7);
            int bcol = lane & 8;
            ldsm_x2(bfh[6], Bsh + brow * AST2 + bcol);
        }
#pragma unroll
        for (int mt = 0; mt < 4; mt++)
#pragma unroll
            for (int nt = 0; nt < 7; nt++)
                mma16816(acc[mt][nt], afh[mt], bfh[nt]);
        __syncthreads();
    }

    auto put = [&](int row, int col, float f) {
        if (MODE == 2) return;
        int b = row / NN, n = row - b * NN;
        int h = col / DD, d = col - h * DD;
        size_t bh = (size_t)b * HH + h;
        __half hi = __float2half_rn(f);
        if (MODE == 0) g_kh [(bh * PROWS + n) * PSTR + d] = hi;
        else           g_vth[(bh * PROWS + d) * PSTR + n] = hi;
    };
#pragma unroll
    for (int mt = 0; mt < 4; mt++)
#pragma unroll
        for (int nt = 0; nt < 7; nt++) {
            int row = m0 + wm * 64 + mt * 16 + (lane >> 2);
            int col = n0 + wn * 56 + nt * 8 + (lane & 3) * 2;
            float b0 = bias[col], b1 = bias[col + 1];
            if (MODE == 2) {
                float2 v0 = make_float2(acc[mt][nt][0] + b0, acc[mt][nt][1] + b1);
                float2 v1 = make_float2(acc[mt][nt][2] + b0, acc[mt][nt][3] + b1);
                *(float2*)(Y + (size_t)row * CC + col) = v0;
                *(float2*)(Y + (size_t)(row + 8) * CC + col) = v1;
            } else {
                put(row,     col,     acc[mt][nt][0] + b0);
                put(row,     col + 1, acc[mt][nt][1] + b1);
                put(row + 8, col,     acc[mt][nt][2] + b0);
                put(row + 8, col + 1, acc[mt][nt][3] + b1);
            }
        }
}

// ============ HMMA logits: L = (Q@K^T)/14 + cp@Q ============================
// tile 112x112, 7 warps (224 thr), warp = 1 m16 x 14 n8. 13 k16 steps (pad 208).
#define TST (112 * AST2)            // 2688 halves per tile
#define LSTG_P2 (4 * TST)           // pass2 stage: 4 tiles

__global__ __launch_bounds__(224) void attn_logits_mma()
{
    extern __shared__ __half sm[];
    const int t    = threadIdx.x;
    const int lane = t & 31;
    const int wid  = t >> 5;        // 0..6
    const int bh   = blockIdx.z;
    const int h    = bh & (HH - 1);
    const int n0   = blockIdx.y * 112;
    const int m0   = blockIdx.x * 112;

    const __half* qh  = g_qh  + (size_t)bh * PROWS * PSTR;
    const __half* kh  = g_kh  + (size_t)bh * PROWS * PSTR;
    const __half* qth = g_qth + (size_t)bh * PROWS * PSTR;
    const __half* qtl = g_qtl + (size_t)bh * PROWS * PSTR;
    const __half* cph = g_cph + (size_t)h * PROWS * PSTR;
    const __half* cpl = g_cpl + (size_t)h * PROWS * PSTR;

    float acc[14][4];
#pragma unroll
    for (int j = 0; j < 14; j++)
#pragma unroll
        for (int r = 0; r < 4; r++) acc[j][r] = 0.f;

    // ---- pass 1: Q@K^T ----
    auto pf1 = [&](int kt) {
        const int k0 = kt * 16;
        __half* st = sm + (kt & 3) * LSTG_P2;
        for (int v = t; v < 448; v += 224) {
            int tile = v / 224, rem = v - tile * 224;
            int row = rem >> 1, ch = rem & 1;
            const __half* g = (tile ? kh + (size_t)(m0 + row) * PSTR
                                    : qh + (size_t)(n0 + row) * PSTR) + k0 + ch * 8;
            CPA16(st + tile * TST + row * AST2 + ch * 8, g);
        }
        CPA_COMMIT();
    };
    pf1(0); pf1(1); pf1(2);
    for (int kt = 0; kt < 13; kt++) {
        if (kt + 3 < 13) pf1(kt + 3);
        else CPA_COMMIT();
        CPA_WAIT3();
        __syncthreads();
        __half* st = sm + (kt & 3) * LSTG_P2;
        unsigned af[4];
        ldsm_x4(af, st + (wid * 16 + (lane & 15)) * AST2 + ((lane >> 4) << 3));
        unsigned bf[14][2];
#pragma unroll
        for (int p = 0; p < 7; p++) {
            int brow = p * 16 + (lane & 7) + ((lane & 16) >> 1);
            ldsm_x4(&bf[2 * p][0], st + TST + brow * AST2 + (lane & 8));
        }
#pragma unroll
        for (int nt = 0; nt < 14; nt++) mma16816(acc[nt], af, bf[nt]);
        __syncthreads();
    }
    asm volatile("cp.async.wait_group 0;");
    __syncthreads();

#pragma unroll
    for (int j = 0; j < 14; j++)
#pragma unroll
        for (int r = 0; r < 4; r++) acc[j][r] *= (1.0f / 14.0f);

    // ---- pass 2: cp@Q, 3-term ----
    auto pf2 = [&](int kt) {
        const int k0 = kt * 16;
        __half* st = sm + (kt & 3) * LSTG_P2;
        for (int v = t; v < 896; v += 224) {
            int tile = v / 224, rem = v - tile * 224;
            int row = rem >> 1, ch = rem & 1;
            const __half* g;
            if (tile == 0)      g = cph + (size_t)(n0 + row) * PSTR + k0 + ch * 8;
            else if (tile == 1) g = cpl + (size_t)(n0 + row) * PSTR + k0 + ch * 8;
            else if (tile == 2) g = qth + (size_t)(m0 + row) * PSTR + k0 + ch * 8;
            else                g = qtl + (size_t)(m0 + row) * PSTR + k0 + ch * 8;
            CPA16(st + tile * TST + row * AST2 + ch * 8, g);
        }
        CPA_COMMIT();
    };
    pf2(0); pf2(1); pf2(2);
    for (int kt = 0; kt < 13; kt++) {
        if (kt + 3 < 13) pf2(kt + 3);
        else CPA_COMMIT();
        CPA_WAIT3();
        __syncthreads();
        __half* st = sm + (kt & 3) * LSTG_P2;
        unsigned afh[4], afl[4];
        int arow = wid * 16 + (lane & 15);
        int acol = (lane >> 4) << 3;
        ldsm_x4(afh, st + arow * AST2 + acol);
        ldsm_x4(afl, st + TST + arow * AST2 + acol);
        unsigned bfh[14][2], bfl[14][2];
#pragma unroll
        for (int p = 0; p < 7; p++) {
            int brow = p * 16 + (lane & 7) + ((lane & 16) >> 1);
            ldsm_x4(&bfh[2 * p][0], st + 2 * TST + brow * AST2 + (lane & 8));
            ldsm_x4(&bfl[2 * p][0], st + 3 * TST + brow * AST2 + (lane & 8));
        }
#pragma unroll
        for (int nt = 0; nt < 14; nt++) mma16816(acc[nt], afh, bfh[nt]);
#pragma unroll
        for (int nt = 0; nt < 14; nt++) mma16816(acc[nt], afl, bfh[nt]);
#pragma unroll
        for (int nt = 0; nt < 14; nt++) mma16816(acc[nt], afh, bfl[nt]);
        __syncthreads();
    }

    // epilogue -> fp32 logits, bounds-checked
    float* Lb = g_L + (size_t)bh * NN * NN;
#pragma unroll
    for (int nt = 0; nt < 14; nt++) {
        int row = n0 + wid * 16 + (lane >> 2);
        int col = m0 + nt * 8 + (lane & 3) * 2;
        if (col < NN) {
            if (row < NN)
                *(float2*)(Lb + (size_t)row * NN + col) =
                    make_float2(acc[nt][0], acc[nt][1]);
            if (row + 8 < NN)
                *(float2*)(Lb + (size_t)(row + 8) * NN + col) =
                    make_float2(acc[nt][2], acc[nt][3]);
        }
    }
}

// ---------------- softmax: fp32 L -> fp16 P (padded layout) -----------------
__global__ __launch_bounds__(256) void softmax_kernel()
{
    const int warp = threadIdx.x >> 5, lane = threadIdx.x & 31;
    const size_t row = (size_t)blockIdx.x * 8 + warp;   // over NBH*NN rows
    const float* p = g_L + row * NN;
    const int bh = (int)(row / NN), n = (int)(row - (size_t)bh * NN);
    __half* po = g_ph + ((size_t)bh * PROWS + n) * PSTR;

    float v[7];
    float mx = -1e30f;
#pragma unroll
    for (int s = 0; s < 7; s++) {
        int idx = lane + s * 32;
        v[s] = (idx < NN) ? p[idx] : -1e30f;
        mx = fmaxf(mx, v[s]);
    }
#pragma unroll
    for (int o = 16; o; o >>= 1) mx = fmaxf(mx, __shfl_xor_sync(0xffffffffu, mx, o));
    float sum = 0.f;
#pragma unroll
    for (int s = 0; s < 7; s++) { v[s] = __expf(v[s] - mx); sum += v[s]; }
#pragma unroll
    for (int o = 16; o; o >>= 1) sum += __shfl_xor_sync(0xffffffffu, sum, o);
    float inv = 1.0f / sum;
#pragma unroll
    for (int s = 0; s < 7; s++) {
        int idx = lane + s * 32;
        if (idx < NN) po[idx] = __float2half_rn(v[s] * inv);
    }
}

// ============ HMMA P@V -> fp16 O (B,N,C) ====================================
#define VSTG (2 * TST)

__global__ __launch_bounds__(224) void attn_pv_mma()
{
    extern __shared__ __half sm[];
    const int t    = threadIdx.x;
    const int lane = t & 31;
    const int wid  = t >> 5;
    const int bh   = blockIdx.z;
    const int b    = bh >> 2, h = bh & 3;
    const int n0   = blockIdx.y * 112;
    const int c0   = blockIdx.x * 112;

    const __half* ph  = g_ph  + (size_t)bh * PROWS * PSTR;
    const __half* vth = g_vth + (size_t)bh * PROWS * PSTR;

    float acc[14][4];
#pragma unroll
    for (int j = 0; j < 14; j++)
#pragma unroll
        for (int r = 0; r < 4; r++) acc[j][r] = 0.f;

    auto pf = [&](int kt) {
        const int k0 = kt * 16;
        __half* st = sm + (kt & 3) * VSTG;
        for (int v = t; v < 448; v += 224) {
            int tile = v / 224, rem = v - tile * 224;
            int row = rem >> 1, ch = rem & 1;
            const __half* g = (tile ? vth + (size_t)(c0 + row) * PSTR
                                    : ph + (size_t)(n0 + row) * PSTR) + k0 + ch * 8;
            CPA16(st + tile * TST + row * AST2 + ch * 8, g);
        }
        CPA_COMMIT();
    };
    pf(0); pf(1); pf(2);
    for (int kt = 0; kt < 13; kt++) {
        if (kt + 3 < 13) pf(kt + 3);
        else CPA_COMMIT();
        CPA_WAIT3();
        __syncthreads();
        __half* st = sm + (kt & 3) * VSTG;
        unsigned af[4];
        ldsm_x4(af, st + (wid * 16 + (lane & 15)) * AST2 + ((lane >> 4) << 3));
        unsigned bf[14][2];
#pragma unroll
        for (int p = 0; p < 7; p++) {
            int brow = p * 16 + (lane & 7) + ((lane & 16) >> 1);
            ldsm_x4(&bf[2 * p][0], st + TST + brow * AST2 + (lane & 8));
        }
#pragma unroll
        for (int nt = 0; nt < 14; nt++) mma16816(acc[nt], af, bf[nt]);
        __syncthreads();
    }

    // epilogue -> g_Oh[(b*196+n)][h*196+c], fp16
#pragma unroll
    for (int nt = 0; nt < 14; nt++) {
        int n = n0 + wid * 16 + (lane >> 2);
        int c = c0 + nt * 8 + (lane & 3) * 2;
        if (c < NN) {
            size_t colo = (size_t)h * DD + c;
            if (n < NN) {
                size_t ro = ((size_t)b * NN + n) * CC + colo;
                g_Oh[ro]     = __float2half_rn(acc[nt][0]);
                g_Oh[ro + 1] = __float2half_rn(acc[nt][1]);
            }
            if (n + 8 < NN) {
                size_t ro = ((size_t)b * NN + n + 8) * CC + colo;
                g_Oh[ro]     = __float2half_rn(acc[nt][2]);
                g_Oh[ro + 1] = __float2half_rn(acc[nt][3]);
            }
        }
    }
}

// ---------------- launcher --------------------------------------------------
extern "C" void kernel_launch(void* const* d_in, const int* in_sizes, int n_in,
                              void* d_out, int out_size)
{
    const float* x     = (const float*)d_in[0];
    const float* Wq    = (const float*)d_in[1];
    const float* bq    = (const float*)d_in[2];
    const float* Wk    = (const float*)d_in[3];
    const float* bk    = (const float*)d_in[4];
    const float* Wv    = (const float*)d_in[5];
    const float* bv    = (const float*)d_in[6];
    const float* Wo    = (const float*)d_in[7];
    const float* bo    = (const float*)d_in[8];
    const float* rel_h = (const float*)d_in[9];
    const float* rel_w = (const float*)d_in[10];
    float* out = (float*)d_out;

    __half *pXh, *pXl, *pOh, *pWqh, *pWql, *pWkh, *pWvh, *pWoh;
    cudaGetSymbolAddress((void**)&pXh,  g_Xh);
    cudaGetSymbolAddress((void**)&pXl,  g_Xl);
    cudaGetSymbolAddress((void**)&pOh,  g_Oh);
    cudaGetSymbolAddress((void**)&pWqh, g_Wqh);
    cudaGetSymbolAddress((void**)&pWql, g_Wql);
    cudaGetSymbolAddress((void**)&pWkh, g_Wkh);
    cudaGetSymbolAddress((void**)&pWvh, g_Wvh);
    cudaGetSymbolAddress((void**)&pWoh, g_Woh);

    const unsigned smem3  = NSTAGE * STG3 * sizeof(__half);   // 92160
    const unsigned smem1  = NSTAGE * STG1 * sizeof(__half);   // 46080
    const unsigned smemL  = 4 * LSTG_P2 * sizeof(__half);     // 86016
    const unsigned smemV  = 4 * VSTG * sizeof(__half);        // 43008
    cudaFuncSetAttribute(hgemm_proj3,
        cudaFuncAttributeMaxDynamicSharedMemorySize, smem3);
    cudaFuncSetAttribute(hgemm_proj1<0>,
        cudaFuncAttributeMaxDynamicSharedMemorySize, smem1);
    cudaFuncSetAttribute(hgemm_proj1<1>,
        cudaFuncAttributeMaxDynamicSharedMemorySize, smem1);
    cudaFuncSetAttribute(hgemm_proj1<2>,
        cudaFuncAttributeMaxDynamicSharedMemorySize, smem1);
    cudaFuncSetAttribute(attn_logits_mma,
        cudaFuncAttributeMaxDynamicSharedMemorySize, smemL);
    cudaFuncSetAttribute(attn_pv_mma,
        cudaFuncAttributeMaxDynamicSharedMemorySize, smemV);

    const int xn = MM * CC;
    const int wn = CC * CC;
    // launch order keeps the ncu slot (-s 5 -c 1) on a heavy GEMM
    f2h_split_kernel<<<(xn + 255) / 256, 256>>>(x, pXh, pXl, xn);      // 1
    wconv_kernel<<<(4 * wn + 255) / 256, 256>>>(Wq, Wk, Wv, Wo);       // 2
    cp_split_kernel<<<(HH * NN * DD + 255) / 256, 256>>>(rel_h, rel_w);// 3

    dim3 pgrid(CC / 112, MM / 128);   // (7, 392)
    hgemm_proj3<<<pgrid, 128, smem3>>>(pXh, pXl, pWqh, pWql, bq);      // 4
    hgemm_proj1<0><<<pgrid, 128, smem1>>>(pXh, pWkh, bk, nullptr);     // 5
    hgemm_proj1<1><<<pgrid, 128, smem1>>>(pXh, pWvh, bv, nullptr);     // 6 <- profiled

    attn_logits_mma<<<dim3(2, 2, NBH), 224, smemL>>>();
    softmax_kernel<<<NBH * NN / 8, 256>>>();
    attn_pv_mma<<<dim3(2, 2, NBH), 224, smemV>>>();

    hgemm_proj1<2><<<pgrid, 128, smem1>>>(pOh, pWoh, bo, out);
}

// round 15
// speedup vs baseline: 1.0250x; 1.0250x over previous
#include <cuda_runtime.h>
#include <cuda_fp16.h>
#include <math.h>

#define BB 256
#define NN 196
#define CC 784
#define HH 4
#define DD 196
#define MM (BB*NN)          // 50176 tokens
#define PSTR 216            // padded col stride (halves) for attn operands
#define PROWS 256           // padded rows per (b,h)
#define NBH (BB*HH)

// ---------------- scratch (device globals; pads rely on zero-init) ----------
__device__ __align__(16) float  g_L[(size_t)NBH * NN * NN];
__device__ __align__(16) __half g_Xh[(size_t)MM * CC];
__device__ __align__(16) __half g_Xl[(size_t)MM * CC];
__device__ __align__(16) __half g_Oh[(size_t)MM * CC];
__device__ __align__(16) __half g_Wqh[CC * CC];
__device__ __align__(16) __half g_Wql[CC * CC];
__device__ __align__(16) __half g_Wkh[CC * CC];
__device__ __align__(16) __half g_Wvh[CC * CC];
__device__ __align__(16) __half g_Woh[CC * CC];
// attention operands, padded [bh][PROWS][PSTR]; pads stay zero forever
__device__ __align__(16) __half g_qh [(size_t)NBH * PROWS * PSTR];
__device__ __align__(16) __half g_ql [(size_t)NBH * PROWS * PSTR];
__device__ __align__(16) __half g_qth[(size_t)NBH * PROWS * PSTR];
__device__ __align__(16) __half g_qtl[(size_t)NBH * PROWS * PSTR];
__device__ __align__(16) __half g_kh [(size_t)NBH * PROWS * PSTR];
__device__ __align__(16) __half g_vth[(size_t)NBH * PROWS * PSTR];
__device__ __align__(16) __half g_ph [(size_t)NBH * PROWS * PSTR];
__device__ __align__(16) __half g_cph[HH * PROWS * PSTR];
__device__ __align__(16) __half g_cpl[HH * PROWS * PSTR];

// ---------------- helpers ----------------------------------------------------
__device__ __forceinline__ void mma16816(float* c, const unsigned* a, const unsigned* b) {
    asm("mma.sync.aligned.m16n8k16.row.col.f32.f16.f16.f32 "
        "{%0,%1,%2,%3}, {%4,%5,%6,%7}, {%8,%9}, {%0,%1,%2,%3};"
        : "+f"(c[0]), "+f"(c[1]), "+f"(c[2]), "+f"(c[3])
        : "r"(a[0]), "r"(a[1]), "r"(a[2]), "r"(a[3]), "r"(b[0]), "r"(b[1]));
}
__device__ __forceinline__ void ldsm_x4(unsigned* d, const __half* p) {
    unsigned s = (unsigned)__cvta_generic_to_shared(p);
    asm volatile("ldmatrix.sync.aligned.m8n8.x4.shared.b16 {%0,%1,%2,%3}, [%4];"
                 : "=r"(d[0]), "=r"(d[1]), "=r"(d[2]), "=r"(d[3]) : "r"(s));
}
__device__ __forceinline__ void ldsm_x2(unsigned* d, const __half* p) {
    unsigned s = (unsigned)__cvta_generic_to_shared(p);
    asm volatile("ldmatrix.sync.aligned.m8n8.x2.shared.b16 {%0,%1}, [%2];"
                 : "=r"(d[0]), "=r"(d[1]) : "r"(s));
}
#define CPA16(s, g) asm volatile("cp.async.cg.shared.global [%0], [%1], 16;" \
    :: "r"((unsigned)__cvta_generic_to_shared(s)), "l"(g))
#define CPA_COMMIT() asm volatile("cp.async.commit_group;")
#define CPA_WAIT3()  asm volatile("cp.async.wait_group 3;")

// ---------------- conversions ------------------------------------------------
__global__ void f2h_split_kernel(const float* __restrict__ in,
                                 __half* __restrict__ hi,
                                 __half* __restrict__ lo, int n) {
    int i = blockIdx.x * blockDim.x + threadIdx.x;
    if (i >= n) return;
    float f = in[i];
    __half h = __float2half_rn(f);
    hi[i] = h;
    lo[i] = __float2half_rn(f - __half2float(h));
}

// all four weights in one launch: Wq -> hi/lo, Wk/Wv/Wo -> hi only
__global__ void wconv_kernel(const float* __restrict__ Wq,
                             const float* __restrict__ Wk,
                             const float* __restrict__ Wv,
                             const float* __restrict__ Wo) {
    const int wn = CC * CC;
    int i = blockIdx.x * blockDim.x + threadIdx.x;
    if (i >= 4 * wn) return;
    int w = i / wn, j = i - w * wn;
    if (w == 0) {
        float f = Wq[j];
        __half h = __float2half_rn(f);
        g_Wqh[j] = h;
        g_Wql[j] = __float2half_rn(f - __half2float(h));
    } else if (w == 1) {
        g_Wkh[j] = __float2half_rn(Wk[j]);
    } else if (w == 2) {
        g_Wvh[j] = __float2half_rn(Wv[j]);
    } else {
        g_Woh[j] = __float2half_rn(Wo[j]);
    }
}

// cp[h][p][k] = rel_h[h,k,p/14] + rel_w[h,k,p%14], split hi/lo, padded
__global__ void cp_split_kernel(const float* __restrict__ rel_h,
                                const float* __restrict__ rel_w) {
    int idx = blockIdx.x * blockDim.x + threadIdx.x;
    if (idx >= HH * NN * DD) return;
    int h   = idx / (NN * DD);
    int rem = idx - h * (NN * DD);
    int p   = rem / DD;
    int k   = rem - p * DD;
    float v = rel_h[(h * DD + k) * 14 + (p / 14)]
            + rel_w[(h * DD + k) * 14 + (p % 14)];
    __half hi = __float2half_rn(v);
    size_t o = ((size_t)h * PROWS + p) * PSTR + k;
    g_cph[o] = hi;
    g_cpl[o] = __float2half_rn(v - __half2float(hi));
}

#define AST2 24
#define NSTAGE 4
#define KITERS 49

// ============ 3-term split-fp16 HMMA GEMM: Q projection ======================
// 8 warps (256 thr), warp tile 32x56 — reg-safe shape (128 regs, occ ~25%).
#define STG3 ((128 + 128 + 112 + 112) * AST2)

__global__ __launch_bounds__(256) void hgemm_proj3(
    const __half* __restrict__ Ah, const __half* __restrict__ Al,
    const __half* __restrict__ Wh, const __half* __restrict__ Wl,
    const float* __restrict__ bias)
{
    extern __shared__ __half sm[];
    const int t    = threadIdx.x;
    const int lane = t & 31;
    const int wid  = t >> 5;
    const int wm   = wid & 3;
    const int wn   = wid >> 2;
    const int m0   = blockIdx.y * 128;
    const int n0   = blockIdx.x * 112;

    float acc[2][7][4];
#pragma unroll
    for (int i = 0; i < 2; i++)
#pragma unroll
        for (int j = 0; j < 7; j++)
#pragma unroll
            for (int r = 0; r < 4; r++) acc[i][j][r] = 0.f;

    auto prefetch = [&](int kt) {
        const int k0 = kt * 16;
        __half* st = sm + (kt & (NSTAGE - 1)) * STG3;
        for (int v = t; v < 960; v += 256) {
            const __half* g; __half* s;
            if (v < 512) {
                int part = v >> 8, rem = v & 255;
                int row = rem >> 1, ch = rem & 1;
                g = (part ? Al : Ah) + (size_t)(m0 + row) * CC + k0 + ch * 8;
                s = st + part * (128 * AST2) + row * AST2 + ch * 8;
            } else {
                int v2 = v - 512;
                int part = v2 / 224, rem = v2 % 224;
                int row = rem >> 1, ch = rem & 1;
                g = (part ? Wl : Wh) + (size_t)(n0 + row) * CC + k0 + ch * 8;
                s = st + 256 * AST2 + part * (112 * AST2) + row * AST2 + ch * 8;
            }
            CPA16(s, g);
        }
        CPA_COMMIT();
    };

    prefetch(0); prefetch(1); prefetch(2);

    for (int kt = 0; kt < KITERS; kt++) {
        if (kt + 3 < KITERS) prefetch(kt + 3);
        else CPA_COMMIT();
        CPA_WAIT3();
        __syncthreads();

        __half* st  = sm + (kt & (NSTAGE - 1)) * STG3;
        __half* Ash = st;
        __half* Asl = st + 128 * AST2;
        __half* Bsh = st + 256 * AST2;
        __half* Bsl = st + 256 * AST2 + 112 * AST2;

        unsigned afh[2][4], afl[2][4];
#pragma unroll
        for (int mt = 0; mt < 2; mt++) {
            int arow = wm * 32 + mt * 16 + (lane & 15);
            int acol = (lane >> 4) << 3;
            ldsm_x4(afh[mt], Ash + arow * AST2 + acol);
            ldsm_x4(afl[mt], Asl + arow * AST2 + acol);
        }
        unsigned bfh[7][2], bfl[7][2];
#pragma unroll
        for (int p = 0; p < 3; p++) {
            int brow = wn * 56 + p * 16 + (lane & 7) + ((lane & 16) >> 1);
            int bcol = lane & 8;
            ldsm_x4(&bfh[2 * p][0], Bsh + brow * AST2 + bcol);
            ldsm_x4(&bfl[2 * p][0], Bsl + brow * AST2 + bcol);
        }
        {
            int brow = wn * 56 + 48 + (lane & 7);
            int bcol = lane & 8;
            ldsm_x2(bfh[6], Bsh + brow * AST2 + bcol);
            ldsm_x2(bfl[6], Bsl + brow * AST2 + bcol);
        }
#pragma unroll
        for (int mt = 0; mt < 2; mt++)
#pragma unroll
            for (int nt = 0; nt < 7; nt++)
                mma16816(acc[mt][nt], afh[mt], bfh[nt]);
#pragma unroll
        for (int mt = 0; mt < 2; mt++)
#pragma unroll
            for (int nt = 0; nt < 7; nt++)
                mma16816(acc[mt][nt], afh[mt], bfl[nt]);
#pragma unroll
        for (int mt = 0; mt < 2; mt++)
#pragma unroll
            for (int nt = 0; nt < 7; nt++)
                mma16816(acc[mt][nt], afl[mt], bfh[nt]);
        __syncthreads();
    }

    // epilogue: split to hi/lo, write q + q^T padded attention layouts
    auto put = [&](int row, int col, float f) {
        int b = row / NN, n = row - b * NN;
        int h = col / DD, d = col - h * DD;
        size_t bh = (size_t)b * HH + h;
        size_t o1 = (bh * PROWS + n) * PSTR + d;
        size_t o2 = (bh * PROWS + d) * PSTR + n;
        __half hi = __float2half_rn(f);
        __half lo = __float2half_rn(f - __half2float(hi));
        g_qh[o1]  = hi; g_ql[o1]  = lo;
        g_qth[o2] = hi; g_qtl[o2] = lo;
    };
#pragma unroll
    for (int mt = 0; mt < 2; mt++)
#pragma unroll
        for (int nt = 0; nt < 7; nt++) {
            int row = m0 + wm * 32 + mt * 16 + (lane >> 2);
            int col = n0 + wn * 56 + nt * 8 + (lane & 3) * 2;
            float b0 = bias[col], b1 = bias[col + 1];
            put(row,     col,     acc[mt][nt][0] + b0);
            put(row,     col + 1, acc[mt][nt][1] + b1);
            put(row + 8, col,     acc[mt][nt][2] + b0);
            put(row + 8, col + 1, acc[mt][nt][3] + b1);
        }
}

// ============ 1-term fp16 HMMA GEMM: K / V / O projections ==================
// MODE 0: K -> g_kh[bh][n][d];  MODE 1: V -> g_vth[bh][d][n];  MODE 2: fp32 Y
// CTA 128 thr, 4 warps, warp tile 64x56 (B-reuse win, fits registers).
#define STG1 ((128 + 112) * AST2)

template<int MODE>
__global__ __launch_bounds__(128) void hgemm_proj1(
    const __half* __restrict__ Ah, const __half* __restrict__ Wh,
    const float* __restrict__ bias, float* __restrict__ Y)
{
    extern __shared__ __half sm[];
    const int t    = threadIdx.x;
    const int lane = t & 31;
    const int wid  = t >> 5;
    const int wm   = wid & 1;
    const int wn   = wid >> 1;
    const int m0   = blockIdx.y * 128;
    const int n0   = blockIdx.x * 112;

    float acc[4][7][4];
#pragma unroll
    for (int i = 0; i < 4; i++)
#pragma unroll
        for (int j = 0; j < 7; j++)
#pragma unroll
            for (int r = 0; r < 4; r++) acc[i][j][r] = 0.f;

    auto prefetch = [&](int kt) {
        const int k0 = kt * 16;
        __half* st = sm + (kt & (NSTAGE - 1)) * STG1;
        for (int v = t; v < 480; v += 128) {
            const __half* g; __half* s;
            if (v < 256) {
                int row = v >> 1, ch = v & 1;
                g = Ah + (size_t)(m0 + row) * CC + k0 + ch * 8;
                s = st + row * AST2 + ch * 8;
            } else {
                int v2 = v - 256;
                int row = v2 >> 1, ch = v2 & 1;
                g = Wh + (size_t)(n0 + row) * CC + k0 + ch * 8;
                s = st + 128 * AST2 + row * AST2 + ch * 8;
            }
            CPA16(s, g);
        }
        CPA_COMMIT();
    };

    prefetch(0); prefetch(1); prefetch(2);

    for (int kt = 0; kt < KITERS; kt++) {
        if (kt + 3 < KITERS) prefetch(kt + 3);
        else CPA_COMMIT();
        CPA_WAIT3();
        __syncthreads();

        __half* st  = sm + (kt & (NSTAGE - 1)) * STG1;
        __half* Ash = st;
        __half* Bsh = st + 128 * AST2;

        unsigned afh[4][4];
#pragma unroll
        for (int mt = 0; mt < 4; mt++) {
            int arow = wm * 64 + mt * 16 + (lane & 15);
            int acol = (lane >> 4) << 3;
            ldsm_x4(afh[mt], Ash + arow * AST2 + acol);
        }
        unsigned bfh[7][2];
#pragma unroll
        for (int p = 0; p < 3; p++) {
            int brow = wn * 56 + p * 16 + (lane & 7) + ((lane & 16) >> 1);
            int bcol = lane & 8;
            ldsm_x4(&bfh[2 * p][0], Bsh + brow * AST2 + bcol);
        }
        {
            int brow = wn * 56 + 48 + (lane & 7);
            int bcol = lane & 8;
            ldsm_x2(bfh[6], Bsh + brow * AST2 + bcol);
        }
#pragma unroll
        for (int mt = 0; mt < 4; mt++)
#pragma unroll
            for (int nt = 0; nt < 7; nt++)
                mma16816(acc[mt][nt], afh[mt], bfh[nt]);
        __syncthreads();
    }

    auto put = [&](int row, int col, float f) {
        if (MODE == 2) return;
        int b = row / NN, n = row - b * NN;
        int h = col / DD, d = col - h * DD;
        size_t bh = (size_t)b * HH + h;
        __half hi = __float2half_rn(f);
        if (MODE == 0) g_kh [(bh * PROWS + n) * PSTR + d] = hi;
        else           g_vth[(bh * PROWS + d) * PSTR + n] = hi;
    };
#pragma unroll
    for (int mt = 0; mt < 4; mt++)
#pragma unroll
        for (int nt = 0; nt < 7; nt++) {
            int row = m0 + wm * 64 + mt * 16 + (lane >> 2);
            int col = n0 + wn * 56 + nt * 8 + (lane & 3) * 2;
            float b0 = bias[col], b1 = bias[col + 1];
            if (MODE == 2) {
                float2 v0 = make_float2(acc[mt][nt][0] + b0, acc[mt][nt][1] + b1);
                float2 v1 = make_float2(acc[mt][nt][2] + b0, acc[mt][nt][3] + b1);
                *(float2*)(Y + (size_t)row * CC + col) = v0;
                *(float2*)(Y + (size_t)(row + 8) * CC + col) = v1;
            } else {
                put(row,     col,     acc[mt][nt][0] + b0);
                put(row,     col + 1, acc[mt][nt][1] + b1);
                put(row + 8, col,     acc[mt][nt][2] + b0);
                put(row + 8, col + 1, acc[mt][nt][3] + b1);
            }
        }
}

// ============ HMMA logits: L = (Q@K^T)/14 + cp@Q ============================
// tile 112x112, 7 warps (224 thr), warp = 1 m16 x 14 n8. 13 k16 steps (pad 208).
#define TST (112 * AST2)            // 2688 halves per tile
#define LSTG_P2 (4 * TST)           // pass2 stage: 4 tiles

__global__ __launch_bounds__(224) void attn_logits_mma()
{
    extern __shared__ __half sm[];
    const int t    = threadIdx.x;
    const int lane = t & 31;
    const int wid  = t >> 5;        // 0..6
    const int bh   = blockIdx.z;
    const int h    = bh & (HH - 1);
    const int n0   = blockIdx.y * 112;
    const int m0   = blockIdx.x * 112;

    const __half* qh  = g_qh  + (size_t)bh * PROWS * PSTR;
    const __half* kh  = g_kh  + (size_t)bh * PROWS * PSTR;
    const __half* qth = g_qth + (size_t)bh * PROWS * PSTR;
    const __half* qtl = g_qtl + (size_t)bh * PROWS * PSTR;
    const __half* cph = g_cph + (size_t)h * PROWS * PSTR;
    const __half* cpl = g_cpl + (size_t)h * PROWS * PSTR;

    float acc[14][4];
#pragma unroll
    for (int j = 0; j < 14; j++)
#pragma unroll
        for (int r = 0; r < 4; r++) acc[j][r] = 0.f;

    // ---- pass 1: Q@K^T ----
    auto pf1 = [&](int kt) {
        const int k0 = kt * 16;
        __half* st = sm + (kt & 3) * LSTG_P2;
        for (int v = t; v < 448; v += 224) {
            int tile = v / 224, rem = v - tile * 224;
            int row = rem >> 1, ch = rem & 1;
            const __half* g = (tile ? kh + (size_t)(m0 + row) * PSTR
                                    : qh + (size_t)(n0 + row) * PSTR) + k0 + ch * 8;
            CPA16(st + tile * TST + row * AST2 + ch * 8, g);
        }
        CPA_COMMIT();
    };
    pf1(0); pf1(1); pf1(2);
    for (int kt = 0; kt < 13; kt++) {
        if (kt + 3 < 13) pf1(kt + 3);
        else CPA_COMMIT();
        CPA_WAIT3();
        __syncthreads();
        __half* st = sm + (kt & 3) * LSTG_P2;
        unsigned af[4];
        ldsm_x4(af, st + (wid * 16 + (lane & 15)) * AST2 + ((lane >> 4) << 3));
        unsigned bf[14][2];
#pragma unroll
        for (int p = 0; p < 7; p++) {
            int brow = p * 16 + (lane & 7) + ((lane & 16) >> 1);
            ldsm_x4(&bf[2 * p][0], st + TST + brow * AST2 + (lane & 8));
        }
#pragma unroll
        for (int nt = 0; nt < 14; nt++) mma16816(acc[nt], af, bf[nt]);
        __syncthreads();
    }
    asm volatile("cp.async.wait_group 0;");
    __syncthreads();

#pragma unroll
    for (int j = 0; j < 14; j++)
#pragma unroll
        for (int r = 0; r < 4; r++) acc[j][r] *= (1.0f / 14.0f);

    // ---- pass 2: cp@Q, 3-term ----
    auto pf2 = [&](int kt) {
        const int k0 = kt * 16;
        __half* st = sm + (kt & 3) * LSTG_P2;
        for (int v = t; v < 896; v += 224) {
            int tile = v / 224, rem = v - tile * 224;
            int row = rem >> 1, ch = rem & 1;
            const __half* g;
            if (tile == 0)      g = cph + (size_t)(n0 + row) * PSTR + k0 + ch * 8;
            else if (tile == 1) g = cpl + (size_t)(n0 + row) * PSTR + k0 + ch * 8;
            else if (tile == 2) g = qth + (size_t)(m0 + row) * PSTR + k0 + ch * 8;
            else                g = qtl + (size_t)(m0 + row) * PSTR + k0 + ch * 8;
            CPA16(st + tile * TST + row * AST2 + ch * 8, g);
        }
        CPA_COMMIT();
    };
    pf2(0); pf2(1); pf2(2);
    for (int kt = 0; kt < 13; kt++) {
        if (kt + 3 < 13) pf2(kt + 3);
        else CPA_COMMIT();
        CPA_WAIT3();
        __syncthreads();
        __half* st = sm + (kt & 3) * LSTG_P2;
        unsigned afh[4], afl[4];
        int arow = wid * 16 + (lane & 15);
        int acol = (lane >> 4) << 3;
        ldsm_x4(afh, st + arow * AST2 + acol);
        ldsm_x4(afl, st + TST + arow * AST2 + acol);
        unsigned bfh[14][2], bfl[14][2];
#pragma unroll
        for (int p = 0; p < 7; p++) {
            int brow = p * 16 + (lane & 7) + ((lane & 16) >> 1);
            ldsm_x4(&bfh[2 * p][0], st + 2 * TST + brow * AST2 + (lane & 8));
            ldsm_x4(&bfl[2 * p][0], st + 3 * TST + brow * AST2 + (lane & 8));
        }
#pragma unroll
        for (int nt = 0; nt < 14; nt++) mma16816(acc[nt], afh, bfh[nt]);
#pragma unroll
        for (int nt = 0; nt < 14; nt++) mma16816(acc[nt], afl, bfh[nt]);
#pragma unroll
        for (int nt = 0; nt < 14; nt++) mma16816(acc[nt], afh, bfl[nt]);
        __syncthreads();
    }

    // epilogue -> fp32 logits, bounds-checked
    float* Lb = g_L + (size_t)bh * NN * NN;
#pragma unroll
    for (int nt = 0; nt < 14; nt++) {
        int row = n0 + wid * 16 + (lane >> 2);
        int col = m0 + nt * 8 + (lane & 3) * 2;
        if (col < NN) {
            if (row < NN)
                *(float2*)(Lb + (size_t)row * NN + col) =
                    make_float2(acc[nt][0], acc[nt][1]);
            if (row + 8 < NN)
                *(float2*)(Lb + (size_t)(row + 8) * NN + col) =
                    make_float2(acc[nt][2], acc[nt][3]);
        }
    }
}

// ---------------- softmax: fp32 L -> fp16 P (padded layout) -----------------
__global__ __launch_bounds__(256) void softmax_kernel()
{
    const int warp = threadIdx.x >> 5, lane = threadIdx.x & 31;
    const size_t row = (size_t)blockIdx.x * 8 + warp;   // over NBH*NN rows
    const float* p = g_L + row * NN;
    const int bh = (int)(row / NN), n = (int)(row - (size_t)bh * NN);
    __half* po = g_ph + ((size_t)bh * PROWS + n) * PSTR;

    float v[7];
    float mx = -1e30f;
#pragma unroll
    for (int s = 0; s < 7; s++) {
        int idx = lane + s * 32;
        v[s] = (idx < NN) ? p[idx] : -1e30f;
        mx = fmaxf(mx, v[s]);
    }
#pragma unroll
    for (int o = 16; o; o >>= 1) mx = fmaxf(mx, __shfl_xor_sync(0xffffffffu, mx, o));
    float sum = 0.f;
#pragma unroll
    for (int s = 0; s < 7; s++) { v[s] = __expf(v[s] - mx); sum += v[s]; }
#pragma unroll
    for (int o = 16; o; o >>= 1) sum += __shfl_xor_sync(0xffffffffu, sum, o);
    float inv = 1.0f / sum;
#pragma unroll
    for (int s = 0; s < 7; s++) {
        int idx = lane + s * 32;
        if (idx < NN) po[idx] = __float2half_rn(v[s] * inv);
    }
}

// ============ HMMA P@V -> fp16 O (B,N,C) ====================================
#define VSTG (2 * TST)

__global__ __launch_bounds__(224) void attn_pv_mma()
{
    extern __shared__ __half sm[];
    const int t    = threadIdx.x;
    const int lane = t & 31;
    const int wid  = t >> 5;
    const int bh   = blockIdx.z;
    const int b    = bh >> 2, h = bh & 3;
    const int n0   = blockIdx.y * 112;
    const int c0   = blockIdx.x * 112;

    const __half* ph  = g_ph  + (size_t)bh * PROWS * PSTR;
    const __half* vth = g_vth + (size_t)bh * PROWS * PSTR;

    float acc[14][4];
#pragma unroll
    for (int j = 0; j < 14; j++)
#pragma unroll
        for (int r = 0; r < 4; r++) acc[j][r] = 0.f;

    auto pf = [&](int kt) {
        const int k0 = kt * 16;
        __half* st = sm + (kt & 3) * VSTG;
        for (int v = t; v < 448; v += 224) {
            int tile = v / 224, rem = v - tile * 224;
            int row = rem >> 1, ch = rem & 1;
            const __half* g = (tile ? vth + (size_t)(c0 + row) * PSTR
                                    : ph + (size_t)(n0 + row) * PSTR) + k0 + ch * 8;
            CPA16(st + tile * TST + row * AST2 + ch * 8, g);
        }
        CPA_COMMIT();
    };
    pf(0); pf(1); pf(2);
    for (int kt = 0; kt < 13; kt++) {
        if (kt + 3 < 13) pf(kt + 3);
        else CPA_COMMIT();
        CPA_WAIT3();
        __syncthreads();
        __half* st = sm + (kt & 3) * VSTG;
        unsigned af[4];
        ldsm_x4(af, st + (wid * 16 + (lane & 15)) * AST2 + ((lane >> 4) << 3));
        unsigned bf[14][2];
#pragma unroll
        for (int p = 0; p < 7; p++) {
            int brow = p * 16 + (lane & 7) + ((lane & 16) >> 1);
            ldsm_x4(&bf[2 * p][0], st + TST + brow * AST2 + (lane & 8));
        }
#pragma unroll
        for (int nt = 0; nt < 14; nt++) mma16816(acc[nt], af, bf[nt]);
        __syncthreads();
    }

    // epilogue -> g_Oh[(b*196+n)][h*196+c], fp16
#pragma unroll
    for (int nt = 0; nt < 14; nt++) {
        int n = n0 + wid * 16 + (lane >> 2);
        int c = c0 + nt * 8 + (lane & 3) * 2;
        if (c < NN) {
            size_t colo = (size_t)h * DD + c;
            if (n < NN) {
                size_t ro = ((size_t)b * NN + n) * CC + colo;
                g_Oh[ro]     = __float2half_rn(acc[nt][0]);
                g_Oh[ro + 1] = __float2half_rn(acc[nt][1]);
            }
            if (n + 8 < NN) {
                size_t ro = ((size_t)b * NN + n + 8) * CC + colo;
                g_Oh[ro]     = __float2half_rn(acc[nt][2]);
                g_Oh[ro + 1] = __float2half_rn(acc[nt][3]);
            }
        }
    }
}

// ---------------- launcher --------------------------------------------------
extern "C" void kernel_launch(void* const* d_in, const int* in_sizes, int n_in,
                              void* d_out, int out_size)
{
    const float* x     = (const float*)d_in[0];
    const float* Wq    = (const float*)d_in[1];
    const float* bq    = (const float*)d_in[2];
    const float* Wk    = (const float*)d_in[3];
    const float* bk    = (const float*)d_in[4];
    const float* Wv    = (const float*)d_in[5];
    const float* bv    = (const float*)d_in[6];
    const float* Wo    = (const float*)d_in[7];
    const float* bo    = (const float*)d_in[8];
    const float* rel_h = (const float*)d_in[9];
    const float* rel_w = (const float*)d_in[10];
    float* out = (float*)d_out;

    __half *pXh, *pXl, *pOh, *pWqh, *pWql, *pWkh, *pWvh, *pWoh;
    cudaGetSymbolAddress((void**)&pXh,  g_Xh);
    cudaGetSymbolAddress((void**)&pXl,  g_Xl);
    cudaGetSymbolAddress((void**)&pOh,  g_Oh);
    cudaGetSymbolAddress((void**)&pWqh, g_Wqh);
    cudaGetSymbolAddress((void**)&pWql, g_Wql);
    cudaGetSymbolAddress((void**)&pWkh, g_Wkh);
    cudaGetSymbolAddress((void**)&pWvh, g_Wvh);
    cudaGetSymbolAddress((void**)&pWoh, g_Woh);

    const unsigned smem3  = NSTAGE * STG3 * sizeof(__half);   // 92160
    const unsigned smem1  = NSTAGE * STG1 * sizeof(__half);   // 46080
    const unsigned smemL  = 4 * LSTG_P2 * sizeof(__half);     // 86016
    const unsigned smemV  = 4 * VSTG * sizeof(__half);        // 43008
    cudaFuncSetAttribute(hgemm_proj3,
        cudaFuncAttributeMaxDynamicSharedMemorySize, smem3);
    cudaFuncSetAttribute(hgemm_proj1<0>,
        cudaFuncAttributeMaxDynamicSharedMemorySize, smem1);
    cudaFuncSetAttribute(hgemm_proj1<1>,
        cudaFuncAttributeMaxDynamicSharedMemorySize, smem1);
    cudaFuncSetAttribute(hgemm_proj1<2>,
        cudaFuncAttributeMaxDynamicSharedMemorySize, smem1);
    cudaFuncSetAttribute(attn_logits_mma,
        cudaFuncAttributeMaxDynamicSharedMemorySize, smemL);
    cudaFuncSetAttribute(attn_pv_mma,
        cudaFuncAttributeMaxDynamicSharedMemorySize, smemV);

    const int xn = MM * CC;
    const int wn = CC * CC;
    // launch order keeps the ncu slot (-s 5 -c 1) on a heavy GEMM
    f2h_split_kernel<<<(xn + 255) / 256, 256>>>(x, pXh, pXl, xn);      // 1
    wconv_kernel<<<(4 * wn + 255) / 256, 256>>>(Wq, Wk, Wv, Wo);       // 2
    cp_split_kernel<<<(HH * NN * DD + 255) / 256, 256>>>(rel_h, rel_w);// 3

    dim3 pgrid(CC / 112, MM / 128);   // (7, 392)
    hgemm_proj3<<<pgrid, 256, smem3>>>(pXh, pXl, pWqh, pWql, bq);      // 4
    hgemm_proj1<0><<<pgrid, 128, smem1>>>(pXh, pWkh, bk, nullptr);     // 5
    hgemm_proj1<1><<<pgrid, 128, smem1>>>(pXh, pWvh, bv, nullptr);     // 6 <- profiled

    attn_logits_mma<<<dim3(2, 2, NBH), 224, smemL>>>();
    softmax_kernel<<<NBH * NN / 8, 256>>>();
    attn_pv_mma<<<dim3(2, 2, NBH), 224, smemV>>>();

    hgemm_proj1<2><<<pgrid, 128, smem1>>>(pOh, pWoh, bo, out);
}

// round 16
// speedup vs baseline: 1.0804x; 1.0541x over previous
#include <cuda_runtime.h>
#include <cuda_fp16.h>
#include <math.h>

#define BB 256
#define NN 196
#define CC 784
#define HH 4
#define DD 196
#define MM (BB*NN)          // 50176 tokens
#define PSTR 216            // padded col stride (halves) for attn operands
#define PROWS 256           // padded rows per (b,h)
#define NBH (BB*HH)

// ---------------- scratch (device globals; pads rely on zero-init) ----------
__device__ __align__(16) __half g_Xh[(size_t)MM * CC];
__device__ __align__(16) __half g_Xl[(size_t)MM * CC];
__device__ __align__(16) __half g_Oh[(size_t)MM * CC];
__device__ __align__(16) __half g_Wqh[CC * CC];
__device__ __align__(16) __half g_Wql[CC * CC];
__device__ __align__(16) __half g_Wkh[CC * CC];
__device__ __align__(16) __half g_Wvh[CC * CC];
__device__ __align__(16) __half g_Woh[CC * CC];
// attention operands, padded [bh][PROWS][PSTR]; pads stay zero forever
__device__ __align__(16) __half g_qh [(size_t)NBH * PROWS * PSTR];
__device__ __align__(16) __half g_ql [(size_t)NBH * PROWS * PSTR];
__device__ __align__(16) __half g_qth[(size_t)NBH * PROWS * PSTR];
__device__ __align__(16) __half g_qtl[(size_t)NBH * PROWS * PSTR];
__device__ __align__(16) __half g_kh [(size_t)NBH * PROWS * PSTR];
__device__ __align__(16) __half g_vth[(size_t)NBH * PROWS * PSTR];
__device__ __align__(16) __half g_ph [(size_t)NBH * PROWS * PSTR];
__device__ __align__(16) __half g_cph[HH * PROWS * PSTR];
__device__ __align__(16) __half g_cpl[HH * PROWS * PSTR];

// ---------------- helpers ----------------------------------------------------
__device__ __forceinline__ void mma16816(float* c, const unsigned* a, const unsigned* b) {
    asm("mma.sync.aligned.m16n8k16.row.col.f32.f16.f16.f32 "
        "{%0,%1,%2,%3}, {%4,%5,%6,%7}, {%8,%9}, {%0,%1,%2,%3};"
        : "+f"(c[0]), "+f"(c[1]), "+f"(c[2]), "+f"(c[3])
        : "r"(a[0]), "r"(a[1]), "r"(a[2]), "r"(a[3]), "r"(b[0]), "r"(b[1]));
}
__device__ __forceinline__ void ldsm_x4(unsigned* d, const __half* p) {
    unsigned s = (unsigned)__cvta_generic_to_shared(p);
    asm volatile("ldmatrix.sync.aligned.m8n8.x4.shared.b16 {%0,%1,%2,%3}, [%4];"
                 : "=r"(d[0]), "=r"(d[1]), "=r"(d[2]), "=r"(d[3]) : "r"(s));
}
__device__ __forceinline__ void ldsm_x2(unsigned* d, const __half* p) {
    unsigned s = (unsigned)__cvta_generic_to_shared(p);
    asm volatile("ldmatrix.sync.aligned.m8n8.x2.shared.b16 {%0,%1}, [%2];"
                 : "=r"(d[0]), "=r"(d[1]) : "r"(s));
}
#define CPA16(s, g) asm volatile("cp.async.cg.shared.global [%0], [%1], 16;" \
    :: "r"((unsigned)__cvta_generic_to_shared(s)), "l"(g))
#define CPA_COMMIT() asm volatile("cp.async.commit_group;")
#define CPA_WAIT3()  asm volatile("cp.async.wait_group 3;")
#define CPA_WAIT2()  asm volatile("cp.async.wait_group 2;")
#define CPA_WAIT0()  asm volatile("cp.async.wait_group 0;")

// ---------------- conversions ------------------------------------------------
__global__ void f2h_split_kernel(const float* __restrict__ in,
                                 __half* __restrict__ hi,
                                 __half* __restrict__ lo, int n) {
    int i = blockIdx.x * blockDim.x + threadIdx.x;
    if (i >= n) return;
    float f = in[i];
    __half h = __float2half_rn(f);
    hi[i] = h;
    lo[i] = __float2half_rn(f - __half2float(h));
}

// all four weights in one launch: Wq -> hi/lo, Wk/Wv/Wo -> hi only
__global__ void wconv_kernel(const float* __restrict__ Wq,
                             const float* __restrict__ Wk,
                             const float* __restrict__ Wv,
                             const float* __restrict__ Wo) {
    const int wn = CC * CC;
    int i = blockIdx.x * blockDim.x + threadIdx.x;
    if (i >= 4 * wn) return;
    int w = i / wn, j = i - w * wn;
    if (w == 0) {
        float f = Wq[j];
        __half h = __float2half_rn(f);
        g_Wqh[j] = h;
        g_Wql[j] = __float2half_rn(f - __half2float(h));
    } else if (w == 1) {
        g_Wkh[j] = __float2half_rn(Wk[j]);
    } else if (w == 2) {
        g_Wvh[j] = __float2half_rn(Wv[j]);
    } else {
        g_Woh[j] = __float2half_rn(Wo[j]);
    }
}

// cp[h][p][k] = rel_h[h,k,p/14] + rel_w[h,k,p%14], split hi/lo, padded
__global__ void cp_split_kernel(const float* __restrict__ rel_h,
                                const float* __restrict__ rel_w) {
    int idx = blockIdx.x * blockDim.x + threadIdx.x;
    if (idx >= HH * NN * DD) return;
    int h   = idx / (NN * DD);
    int rem = idx - h * (NN * DD);
    int p   = rem / DD;
    int k   = rem - p * DD;
    float v = rel_h[(h * DD + k) * 14 + (p / 14)]
            + rel_w[(h * DD + k) * 14 + (p % 14)];
    __half hi = __float2half_rn(v);
    size_t o = ((size_t)h * PROWS + p) * PSTR + k;
    g_cph[o] = hi;
    g_cpl[o] = __float2half_rn(v - __half2float(hi));
}

#define AST2 24
#define NSTAGE 4
#define KITERS 49

// ============ 3-term split-fp16 HMMA GEMM: Q projection ======================
// 8 warps (256 thr), warp tile 32x56 — reg-safe shape (128 regs, occ ~25%).
#define STG3 ((128 + 128 + 112 + 112) * AST2)

__global__ __launch_bounds__(256) void hgemm_proj3(
    const __half* __restrict__ Ah, const __half* __restrict__ Al,
    const __half* __restrict__ Wh, const __half* __restrict__ Wl,
    const float* __restrict__ bias)
{
    extern __shared__ __half sm[];
    const int t    = threadIdx.x;
    const int lane = t & 31;
    const int wid  = t >> 5;
    const int wm   = wid & 3;
    const int wn   = wid >> 2;
    const int m0   = blockIdx.y * 128;
    const int n0   = blockIdx.x * 112;

    float acc[2][7][4];
#pragma unroll
    for (int i = 0; i < 2; i++)
#pragma unroll
        for (int j = 0; j < 7; j++)
#pragma unroll
            for (int r = 0; r < 4; r++) acc[i][j][r] = 0.f;

    auto prefetch = [&](int kt) {
        const int k0 = kt * 16;
        __half* st = sm + (kt & (NSTAGE - 1)) * STG3;
        for (int v = t; v < 960; v += 256) {
            const __half* g; __half* s;
            if (v < 512) {
                int part = v >> 8, rem = v & 255;
                int row = rem >> 1, ch = rem & 1;
                g = (part ? Al : Ah) + (size_t)(m0 + row) * CC + k0 + ch * 8;
                s = st + part * (128 * AST2) + row * AST2 + ch * 8;
            } else {
                int v2 = v - 512;
                int part = v2 / 224, rem = v2 % 224;
                int row = rem >> 1, ch = rem & 1;
                g = (part ? Wl : Wh) + (size_t)(n0 + row) * CC + k0 + ch * 8;
                s = st + 256 * AST2 + part * (112 * AST2) + row * AST2 + ch * 8;
            }
            CPA16(s, g);
        }
        CPA_COMMIT();
    };

    prefetch(0); prefetch(1); prefetch(2);

    for (int kt = 0; kt < KITERS; kt++) {
        if (kt + 3 < KITERS) prefetch(kt + 3);
        else CPA_COMMIT();
        CPA_WAIT3();
        __syncthreads();

        __half* st  = sm + (kt & (NSTAGE - 1)) * STG3;
        __half* Ash = st;
        __half* Asl = st + 128 * AST2;
        __half* Bsh = st + 256 * AST2;
        __half* Bsl = st + 256 * AST2 + 112 * AST2;

        unsigned afh[2][4], afl[2][4];
#pragma unroll
        for (int mt = 0; mt < 2; mt++) {
            int arow = wm * 32 + mt * 16 + (lane & 15);
            int acol = (lane >> 4) << 3;
            ldsm_x4(afh[mt], Ash + arow * AST2 + acol);
            ldsm_x4(afl[mt], Asl + arow * AST2 + acol);
        }
        unsigned bfh[7][2], bfl[7][2];
#pragma unroll
        for (int p = 0; p < 3; p++) {
            int brow = wn * 56 + p * 16 + (lane & 7) + ((lane & 16) >> 1);
            int bcol = lane & 8;
            ldsm_x4(&bfh[2 * p][0], Bsh + brow * AST2 + bcol);
            ldsm_x4(&bfl[2 * p][0], Bsl + brow * AST2 + bcol);
        }
        {
            int brow = wn * 56 + 48 + (lane & 7);
            int bcol = lane & 8;
            ldsm_x2(bfh[6], Bsh + brow * AST2 + bcol);
            ldsm_x2(bfl[6], Bsl + brow * AST2 + bcol);
        }
#pragma unroll
        for (int mt = 0; mt < 2; mt++)
#pragma unroll
            for (int nt = 0; nt < 7; nt++)
                mma16816(acc[mt][nt], afh[mt], bfh[nt]);
#pragma unroll
        for (int mt = 0; mt < 2; mt++)
#pragma unroll
            for (int nt = 0; nt < 7; nt++)
                mma16816(acc[mt][nt], afh[mt], bfl[nt]);
#pragma unroll
        for (int mt = 0; mt < 2; mt++)
#pragma unroll
            for (int nt = 0; nt < 7; nt++)
                mma16816(acc[mt][nt], afl[mt], bfh[nt]);
        __syncthreads();
    }

    // epilogue: split to hi/lo, write q + q^T padded attention layouts
    auto put = [&](int row, int col, float f) {
        int b = row / NN, n = row - b * NN;
        int h = col / DD, d = col - h * DD;
        size_t bh = (size_t)b * HH + h;
        size_t o1 = (bh * PROWS + n) * PSTR + d;
        size_t o2 = (bh * PROWS + d) * PSTR + n;
        __half hi = __float2half_rn(f);
        __half lo = __float2half_rn(f - __half2float(hi));
        g_qh[o1]  = hi; g_ql[o1]  = lo;
        g_qth[o2] = hi; g_qtl[o2] = lo;
    };
#pragma unroll
    for (int mt = 0; mt < 2; mt++)
#pragma unroll
        for (int nt = 0; nt < 7; nt++) {
            int row = m0 + wm * 32 + mt * 16 + (lane >> 2);
            int col = n0 + wn * 56 + nt * 8 + (lane & 3) * 2;
            float b0 = bias[col], b1 = bias[col + 1];
            put(row,     col,     acc[mt][nt][0] + b0);
            put(row,     col + 1, acc[mt][nt][1] + b1);
            put(row + 8, col,     acc[mt][nt][2] + b0);
            put(row + 8, col + 1, acc[mt][nt][3] + b1);
        }
}

// ============ 1-term fp16 HMMA GEMM: K / V / O projections ==================
// MODE 0: K -> g_kh[bh][n][d];  MODE 1: V -> g_vth[bh][d][n];  MODE 2: fp32 Y
// CTA 128 thr, 4 warps, warp tile 64x56 (B-reuse win, fits registers).
#define STG1 ((128 + 112) * AST2)

template<int MODE>
__global__ __launch_bounds__(128) void hgemm_proj1(
    const __half* __restrict__ Ah, const __half* __restrict__ Wh,
    const float* __restrict__ bias, float* __restrict__ Y)
{
    extern __shared__ __half sm[];
    const int t    = threadIdx.x;
    const int lane = t & 31;
    const int wid  = t >> 5;
    const int wm   = wid & 1;
    const int wn   = wid >> 1;
    const int m0   = blockIdx.y * 128;
    const int n0   = blockIdx.x * 112;

    float acc[4][7][4];
#pragma unroll
    for (int i = 0; i < 4; i++)
#pragma unroll
        for (int j = 0; j < 7; j++)
#pragma unroll
            for (int r = 0; r < 4; r++) acc[i][j][r] = 0.f;

    auto prefetch = [&](int kt) {
        const int k0 = kt * 16;
        __half* st = sm + (kt & (NSTAGE - 1)) * STG1;
        for (int v = t; v < 480; v += 128) {
            const __half* g; __half* s;
            if (v < 256) {
                int row = v >> 1, ch = v & 1;
                g = Ah + (size_t)(m0 + row) * CC + k0 + ch * 8;
                s = st + row * AST2 + ch * 8;
            } else {
                int v2 = v - 256;
                int row = v2 >> 1, ch = v2 & 1;
                g = Wh + (size_t)(n0 + row) * CC + k0 + ch * 8;
                s = st + 128 * AST2 + row * AST2 + ch * 8;
            }
            CPA16(s, g);
        }
        CPA_COMMIT();
    };

    prefetch(0); prefetch(1); prefetch(2);

    for (int kt = 0; kt < KITERS; kt++) {
        if (kt + 3 < KITERS) prefetch(kt + 3);
        else CPA_COMMIT();
        CPA_WAIT3();
        __syncthreads();

        __half* st  = sm + (kt & (NSTAGE - 1)) * STG1;
        __half* Ash = st;
        __half* Bsh = st + 128 * AST2;

        unsigned afh[4][4];
#pragma unroll
        for (int mt = 0; mt < 4; mt++) {
            int arow = wm * 64 + mt * 16 + (lane & 15);
            int acol = (lane >> 4) << 3;
            ldsm_x4(afh[mt], Ash + arow * AST2 + acol);
        }
        unsigned bfh[7][2];
#pragma unroll
        for (int p = 0; p < 3; p++) {
            int brow = wn * 56 + p * 16 + (lane & 7) + ((lane & 16) >> 1);
            int bcol = lane & 8;
            ldsm_x4(&bfh[2 * p][0], Bsh + brow * AST2 + bcol);
        }
        {
            int brow = wn * 56 + 48 + (lane & 7);
            int bcol = lane & 8;
            ldsm_x2(bfh[6], Bsh + brow * AST2 + bcol);
        }
#pragma unroll
        for (int mt = 0; mt < 4; mt++)
#pragma unroll
            for (int nt = 0; nt < 7; nt++)
                mma16816(acc[mt][nt], afh[mt], bfh[nt]);
        __syncthreads();
    }

    auto put = [&](int row, int col, float f) {
        if (MODE == 2) return;
        int b = row / NN, n = row - b * NN;
        int h = col / DD, d = col - h * DD;
        size_t bh = (size_t)b * HH + h;
        __half hi = __float2half_rn(f);
        if (MODE == 0) g_kh [(bh * PROWS + n) * PSTR + d] = hi;
        else           g_vth[(bh * PROWS + d) * PSTR + n] = hi;
    };
#pragma unroll
    for (int mt = 0; mt < 4; mt++)
#pragma unroll
        for (int nt = 0; nt < 7; nt++) {
            int row = m0 + wm * 64 + mt * 16 + (lane >> 2);
            int col = n0 + wn * 56 + nt * 8 + (lane & 3) * 2;
            float b0 = bias[col], b1 = bias[col + 1];
            if (MODE == 2) {
                float2 v0 = make_float2(acc[mt][nt][0] + b0, acc[mt][nt][1] + b1);
                float2 v1 = make_float2(acc[mt][nt][2] + b0, acc[mt][nt][3] + b1);
                *(float2*)(Y + (size_t)row * CC + col) = v0;
                *(float2*)(Y + (size_t)(row + 8) * CC + col) = v1;
            } else {
                put(row,     col,     acc[mt][nt][0] + b0);
                put(row,     col + 1, acc[mt][nt][1] + b1);
                put(row + 8, col,     acc[mt][nt][2] + b0);
                put(row + 8, col + 1, acc[mt][nt][3] + b1);
            }
        }
}

// ============ FUSED logits + RPE + softmax -> fp16 P ========================
// grid (2, NBH): CTA owns 112 full logit rows. 7 warps, warp = 1 m16 x 25 n8
// (acc 100 regs). 3-stage cp.async. Pass2 B frags phased in 2 halves.
#define LS_ST (624 * AST2)          // stage: A1 112 | A2 112 | B1 200 | B2 200 rows
#define OFF_A1 0
#define OFF_A2 (112 * AST2)
#define OFF_B1 (224 * AST2)
#define OFF_B2 (424 * AST2)

__global__ __launch_bounds__(224) void attn_lsm()
{
    extern __shared__ __half sm[];
    const int t    = threadIdx.x;
    const int lane = t & 31;
    const int wid  = t >> 5;        // 0..6
    const int bh   = blockIdx.y;
    const int h    = bh & (HH - 1);
    const int n0   = blockIdx.x * 112;

    const __half* qh  = g_qh  + (size_t)bh * PROWS * PSTR;
    const __half* kh  = g_kh  + (size_t)bh * PROWS * PSTR;
    const __half* qth = g_qth + (size_t)bh * PROWS * PSTR;
    const __half* qtl = g_qtl + (size_t)bh * PROWS * PSTR;
    const __half* cph = g_cph + (size_t)h * PROWS * PSTR;
    const __half* cpl = g_cpl + (size_t)h * PROWS * PSTR;

    float acc[25][4];
#pragma unroll
    for (int j = 0; j < 25; j++)
#pragma unroll
        for (int r = 0; r < 4; r++) acc[j][r] = 0.f;

    // ---- pass 1: Q@K^T over all 196 cols (pad 200) ----
    auto pf1 = [&](int kt) {
        const int k0 = kt * 16;
        __half* st = sm + (kt % 3) * LS_ST;
        for (int v = t; v < 624; v += 224) {
            if (v < 224) {
                int row = v >> 1, ch = v & 1;
                CPA16(st + OFF_A1 + row * AST2 + ch * 8,
                      qh + (size_t)(n0 + row) * PSTR + k0 + ch * 8);
            } else {
                int v2 = v - 224;
                int row = v2 >> 1, ch = v2 & 1;
                CPA16(st + OFF_B1 + row * AST2 + ch * 8,
                      kh + (size_t)row * PSTR + k0 + ch * 8);
            }
        }
        CPA_COMMIT();
    };
    pf1(0); pf1(1);
    for (int kt = 0; kt < 13; kt++) {
        if (kt + 2 < 13) pf1(kt + 2);
        else CPA_COMMIT();
        CPA_WAIT2();
        __syncthreads();
        __half* st = sm + (kt % 3) * LS_ST;
        unsigned af[4];
        ldsm_x4(af, st + OFF_A1 + (wid * 16 + (lane & 15)) * AST2 + ((lane >> 4) << 3));
        unsigned bf[25][2];
#pragma unroll
        for (int p = 0; p < 12; p++) {
            int brow = p * 16 + (lane & 7) + ((lane & 16) >> 1);
            ldsm_x4(&bf[2 * p][0], st + OFF_B1 + brow * AST2 + (lane & 8));
        }
        ldsm_x2(bf[24], st + OFF_B1 + (192 + (lane & 7)) * AST2 + (lane & 8));
#pragma unroll
        for (int nt = 0; nt < 25; nt++) mma16816(acc[nt], af, bf[nt]);
        __syncthreads();
    }
    CPA_WAIT0();
    __syncthreads();

#pragma unroll
    for (int j = 0; j < 25; j++)
#pragma unroll
        for (int r = 0; r < 4; r++) acc[j][r] *= (1.0f / 14.0f);

    // ---- pass 2: cp@Q, 3-term, B phased in 2 halves ----
    auto pf2 = [&](int kt) {
        const int k0 = kt * 16;
        __half* st = sm + (kt % 3) * LS_ST;
        for (int v = t; v < 1248; v += 224) {
            if (v < 224) {
                int row = v >> 1, ch = v & 1;
                CPA16(st + OFF_A1 + row * AST2 + ch * 8,
                      cph + (size_t)(n0 + row) * PSTR + k0 + ch * 8);
            } else if (v < 448) {
                int v2 = v - 224;
                int row = v2 >> 1, ch = v2 & 1;
                CPA16(st + OFF_A2 + row * AST2 + ch * 8,
                      cpl + (size_t)(n0 + row) * PSTR + k0 + ch * 8);
            } else if (v < 848) {
                int v2 = v - 448;
                int row = v2 >> 1, ch = v2 & 1;
                CPA16(st + OFF_B1 + row * AST2 + ch * 8,
                      qth + (size_t)row * PSTR + k0 + ch * 8);
            } else {
                int v2 = v - 848;
                int row = v2 >> 1, ch = v2 & 1;
                CPA16(st + OFF_B2 + row * AST2 + ch * 8,
                      qtl + (size_t)row * PSTR + k0 + ch * 8);
            }
        }
        CPA_COMMIT();
    };
    pf2(0); pf2(1);
    for (int kt = 0; kt < 13; kt++) {
        if (kt + 2 < 13) pf2(kt + 2);
        else CPA_COMMIT();
        CPA_WAIT2();
        __syncthreads();
        __half* st = sm + (kt % 3) * LS_ST;
        unsigned afh[4], afl[4];
        int arow = wid * 16 + (lane & 15);
        int acol = (lane >> 4) << 3;
        ldsm_x4(afh, st + OFF_A1 + arow * AST2 + acol);
        ldsm_x4(afl, st + OFF_A2 + arow * AST2 + acol);
        // half 1: tiles 0..11
        {
            unsigned bfh[12][2], bfl[12][2];
#pragma unroll
            for (int p = 0; p < 6; p++) {
                int brow = p * 16 + (lane & 7) + ((lane & 16) >> 1);
                ldsm_x4(&bfh[2 * p][0], st + OFF_B1 + brow * AST2 + (lane & 8));
                ldsm_x4(&bfl[2 * p][0], st + OFF_B2 + brow * AST2 + (lane & 8));
            }
#pragma unroll
            for (int nt = 0; nt < 12; nt++) mma16816(acc[nt], afh, bfh[nt]);
#pragma unroll
            for (int nt = 0; nt < 12; nt++) mma16816(acc[nt], afl, bfh[nt]);
#pragma unroll
            for (int nt = 0; nt < 12; nt++) mma16816(acc[nt], afh, bfl[nt]);
        }
        // half 2: tiles 12..24
        {
            unsigned bfh[13][2], bfl[13][2];
#pragma unroll
            for (int p = 0; p < 6; p++) {
                int brow = 96 + p * 16 + (lane & 7) + ((lane & 16) >> 1);
                ldsm_x4(&bfh[2 * p][0], st + OFF_B1 + brow * AST2 + (lane & 8));
                ldsm_x4(&bfl[2 * p][0], st + OFF_B2 + brow * AST2 + (lane & 8));
            }
            ldsm_x2(bfh[12], st + OFF_B1 + (192 + (lane & 7)) * AST2 + (lane & 8));
            ldsm_x2(bfl[12], st + OFF_B2 + (192 + (lane & 7)) * AST2 + (lane & 8));
#pragma unroll
            for (int nt = 0; nt < 13; nt++) mma16816(acc[12 + nt], afh, bfh[nt]);
#pragma unroll
            for (int nt = 0; nt < 13; nt++) mma16816(acc[12 + nt], afl, bfh[nt]);
#pragma unroll
            for (int nt = 0; nt < 13; nt++) mma16816(acc[12 + nt], afh, bfl[nt]);
        }
        __syncthreads();
    }

    // ---- epilogue: softmax per row in-register -> fp16 P ----
#pragma unroll
    for (int hf = 0; hf < 2; hf++) {
        int lr = n0 + wid * 16 + (lane >> 2) + hf * 8;
        const int c0 = hf * 2;
        float mx = -1e30f;
#pragma unroll
        for (int nt = 0; nt < 25; nt++) {
            int col = nt * 8 + (lane & 3) * 2;
            if (col >= NN)     { acc[nt][c0] = -1e30f; acc[nt][c0 + 1] = -1e30f; }
            else if (col + 1 >= NN) { acc[nt][c0 + 1] = -1e30f; }
            mx = fmaxf(mx, fmaxf(acc[nt][c0], acc[nt][c0 + 1]));
        }
        mx = fmaxf(mx, __shfl_xor_sync(0xffffffffu, mx, 1));
        mx = fmaxf(mx, __shfl_xor_sync(0xffffffffu, mx, 2));
        float sum = 0.f;
#pragma unroll
        for (int nt = 0; nt < 25; nt++) {
            float e0 = __expf(acc[nt][c0]     - mx);
            float e1 = __expf(acc[nt][c0 + 1] - mx);
            acc[nt][c0] = e0; acc[nt][c0 + 1] = e1;
            sum += e0 + e1;
        }
        sum += __shfl_xor_sync(0xffffffffu, sum, 1);
        sum += __shfl_xor_sync(0xffffffffu, sum, 2);
        float inv = 1.0f / sum;
        if (lr < NN) {
            __half* po = g_ph + ((size_t)bh * PROWS + lr) * PSTR;
#pragma unroll
            for (int nt = 0; nt < 25; nt++) {
                int col = nt * 8 + (lane & 3) * 2;
                if (col < NN)
                    *(__half2*)(po + col) =
                        __floats2half2_rn(acc[nt][c0] * inv, acc[nt][c0 + 1] * inv);
            }
        }
    }
}

// ============ HMMA P@V -> fp16 O (B,N,C) ====================================
#define TST (112 * AST2)
#define VSTG (2 * TST)

__global__ __launch_bounds__(224) void attn_pv_mma()
{
    extern __shared__ __half sm[];
    const int t    = threadIdx.x;
    const int lane = t & 31;
    const int wid  = t >> 5;
    const int bh   = blockIdx.z;
    const int b    = bh >> 2, h = bh & 3;
    const int n0   = blockIdx.y * 112;
    const int c0   = blockIdx.x * 112;

    const __half* ph  = g_ph  + (size_t)bh * PROWS * PSTR;
    const __half* vth = g_vth + (size_t)bh * PROWS * PSTR;

    float acc[14][4];
#pragma unroll
    for (int j = 0; j < 14; j++)
#pragma unroll
        for (int r = 0; r < 4; r++) acc[j][r] = 0.f;

    auto pf = [&](int kt) {
        const int k0 = kt * 16;
        __half* st = sm + (kt & 3) * VSTG;
        for (int v = t; v < 448; v += 224) {
            int tile = v / 224, rem = v - tile * 224;
            int row = rem >> 1, ch = rem & 1;
            const __half* g = (tile ? vth + (size_t)(c0 + row) * PSTR
                                    : ph + (size_t)(n0 + row) * PSTR) + k0 + ch * 8;
            CPA16(st + tile * TST + row * AST2 + ch * 8, g);
        }
        CPA_COMMIT();
    };
    pf(0); pf(1); pf(2);
    for (int kt = 0; kt < 13; kt++) {
        if (kt + 3 < 13) pf(kt + 3);
        else CPA_COMMIT();
        CPA_WAIT3();
        __syncthreads();
        __half* st = sm + (kt & 3) * VSTG;
        unsigned af[4];
        ldsm_x4(af, st + (wid * 16 + (lane & 15)) * AST2 + ((lane >> 4) << 3));
        unsigned bf[14][2];
#pragma unroll
        for (int p = 0; p < 7; p++) {
            int brow = p * 16 + (lane & 7) + ((lane & 16) >> 1);
            ldsm_x4(&bf[2 * p][0], st + TST + brow * AST2 + (lane & 8));
        }
#pragma unroll
        for (int nt = 0; nt < 14; nt++) mma16816(acc[nt], af, bf[nt]);
        __syncthreads();
    }

    // epilogue -> g_Oh[(b*196+n)][h*196+c], fp16
#pragma unroll
    for (int nt = 0; nt < 14; nt++) {
        int n = n0 + wid * 16 + (lane >> 2);
        int c = c0 + nt * 8 + (lane & 3) * 2;
        if (c < NN) {
            size_t colo = (size_t)h * DD + c;
            if (n < NN) {
                size_t ro = ((size_t)b * NN + n) * CC + colo;
                g_Oh[ro]     = __float2half_rn(acc[nt][0]);
                g_Oh[ro + 1] = __float2half_rn(acc[nt][1]);
            }
            if (n + 8 < NN) {
                size_t ro = ((size_t)b * NN + n + 8) * CC + colo;
                g_Oh[ro]     = __float2half_rn(acc[nt][2]);
                g_Oh[ro + 1] = __float2half_rn(acc[nt][3]);
            }
        }
    }
}

// ---------------- launcher --------------------------------------------------
extern "C" void kernel_launch(void* const* d_in, const int* in_sizes, int n_in,
                              void* d_out, int out_size)
{
    const float* x     = (const float*)d_in[0];
    const float* Wq    = (const float*)d_in[1];
    const float* bq    = (const float*)d_in[2];
    const float* Wk    = (const float*)d_in[3];
    const float* bk    = (const float*)d_in[4];
    const float* Wv    = (const float*)d_in[5];
    const float* bv    = (const float*)d_in[6];
    const float* Wo    = (const float*)d_in[7];
    const float* bo    = (const float*)d_in[8];
    const float* rel_h = (const float*)d_in[9];
    const float* rel_w = (const float*)d_in[10];
    float* out = (float*)d_out;

    __half *pXh, *pXl, *pOh, *pWqh, *pWql, *pWkh, *pWvh, *pWoh;
    cudaGetSymbolAddress((void**)&pXh,  g_Xh);
    cudaGetSymbolAddress((void**)&pXl,  g_Xl);
    cudaGetSymbolAddress((void**)&pOh,  g_Oh);
    cudaGetSymbolAddress((void**)&pWqh, g_Wqh);
    cudaGetSymbolAddress((void**)&pWql, g_Wql);
    cudaGetSymbolAddress((void**)&pWkh, g_Wkh);
    cudaGetSymbolAddress((void**)&pWvh, g_Wvh);
    cudaGetSymbolAddress((void**)&pWoh, g_Woh);

    const unsigned smem3  = NSTAGE * STG3 * sizeof(__half);   // 92160
    const unsigned smem1  = NSTAGE * STG1 * sizeof(__half);   // 46080
    const unsigned smemLS = 3 * LS_ST * sizeof(__half);       // 89856
    const unsigned smemV  = 4 * VSTG * sizeof(__half);        // 43008
    cudaFuncSetAttribute(hgemm_proj3,
        cudaFuncAttributeMaxDynamicSharedMemorySize, smem3);
    cudaFuncSetAttribute(hgemm_proj1<0>,
        cudaFuncAttributeMaxDynamicSharedMemorySize, smem1);
    cudaFuncSetAttribute(hgemm_proj1<1>,
        cudaFuncAttributeMaxDynamicSharedMemorySize, smem1);
    cudaFuncSetAttribute(hgemm_proj1<2>,
        cudaFuncAttributeMaxDynamicSharedMemorySize, smem1);
    cudaFuncSetAttribute(attn_lsm,
        cudaFuncAttributeMaxDynamicSharedMemorySize, smemLS);
    cudaFuncSetAttribute(attn_pv_mma,
        cudaFuncAttributeMaxDynamicSharedMemorySize, smemV);

    const int xn = MM * CC;
    const int wn = CC * CC;
    // launch order keeps the ncu slot (-s 5 -c 1) on a heavy GEMM
    f2h_split_kernel<<<(xn + 255) / 256, 256>>>(x, pXh, pXl, xn);      // 1
    wconv_kernel<<<(4 * wn + 255) / 256, 256>>>(Wq, Wk, Wv, Wo);       // 2
    cp_split_kernel<<<(HH * NN * DD + 255) / 256, 256>>>(rel_h, rel_w);// 3

    dim3 pgrid(CC / 112, MM / 128);   // (7, 392)
    hgemm_proj3<<<pgrid, 256, smem3>>>(pXh, pXl, pWqh, pWql, bq);      // 4
    hgemm_proj1<0><<<pgrid, 128, smem1>>>(pXh, pWkh, bk, nullptr);     // 5
    hgemm_proj1<1><<<pgrid, 128, smem1>>>(pXh, pWvh, bv, nullptr);     // 6 <- profiled

    attn_lsm<<<dim3(2, NBH), 224, smemLS>>>();
    attn_pv_mma<<<dim3(2, 2, NBH), 224, smemV>>>();

    hgemm_proj1<2><<<pgrid, 128, smem1>>>(pOh, pWoh, bo, out);
}

// round 17
// speedup vs baseline: 1.1122x; 1.0295x over previous
#include <cuda_runtime.h>
#include <cuda_fp16.h>
#include <math.h>

#define BB 256
#define NN 196
#define CC 784
#define HH 4
#define DD 196
#define MM (BB*NN)          // 50176 tokens
#define PSTR 216            // padded col stride (halves) for attn operands
#define PROWS 256           // padded rows per (b,h)
#define NBH (BB*HH)

// ---------------- scratch (device globals; pads rely on zero-init) ----------
__device__ __align__(16) __half g_Xh[(size_t)MM * CC];
__device__ __align__(16) __half g_Xl[(size_t)MM * CC];
__device__ __align__(16) __half g_Oh[(size_t)MM * CC];
__device__ __align__(16) __half g_Wqh[CC * CC];
__device__ __align__(16) __half g_Wql[CC * CC];
__device__ __align__(16) __half g_Wkh[CC * CC];
__device__ __align__(16) __half g_Wvh[CC * CC];
__device__ __align__(16) __half g_Woh[CC * CC];
// attention operands, padded [bh][PROWS][PSTR]; pads stay zero forever
__device__ __align__(16) __half g_qh [(size_t)NBH * PROWS * PSTR];
__device__ __align__(16) __half g_ql [(size_t)NBH * PROWS * PSTR];
__device__ __align__(16) __half g_qth[(size_t)NBH * PROWS * PSTR];
__device__ __align__(16) __half g_qtl[(size_t)NBH * PROWS * PSTR];
__device__ __align__(16) __half g_kh [(size_t)NBH * PROWS * PSTR];
__device__ __align__(16) __half g_vth[(size_t)NBH * PROWS * PSTR];
__device__ __align__(16) __half g_ph [(size_t)NBH * PROWS * PSTR];
__device__ __align__(16) __half g_cph[HH * PROWS * PSTR];
__device__ __align__(16) __half g_cpl[HH * PROWS * PSTR];

// ---------------- helpers ----------------------------------------------------
__device__ __forceinline__ void mma16816(float* c, const unsigned* a, const unsigned* b) {
    asm("mma.sync.aligned.m16n8k16.row.col.f32.f16.f16.f32 "
        "{%0,%1,%2,%3}, {%4,%5,%6,%7}, {%8,%9}, {%0,%1,%2,%3};"
        : "+f"(c[0]), "+f"(c[1]), "+f"(c[2]), "+f"(c[3])
        : "r"(a[0]), "r"(a[1]), "r"(a[2]), "r"(a[3]), "r"(b[0]), "r"(b[1]));
}
__device__ __forceinline__ void ldsm_x4(unsigned* d, const __half* p) {
    unsigned s = (unsigned)__cvta_generic_to_shared(p);
    asm volatile("ldmatrix.sync.aligned.m8n8.x4.shared.b16 {%0,%1,%2,%3}, [%4];"
                 : "=r"(d[0]), "=r"(d[1]), "=r"(d[2]), "=r"(d[3]) : "r"(s));
}
__device__ __forceinline__ void ldsm_x2(unsigned* d, const __half* p) {
    unsigned s = (unsigned)__cvta_generic_to_shared(p);
    asm volatile("ldmatrix.sync.aligned.m8n8.x2.shared.b16 {%0,%1}, [%2];"
                 : "=r"(d[0]), "=r"(d[1]) : "r"(s));
}
#define CPA16(s, g) asm volatile("cp.async.cg.shared.global [%0], [%1], 16;" \
    :: "r"((unsigned)__cvta_generic_to_shared(s)), "l"(g))
#define CPA_COMMIT() asm volatile("cp.async.commit_group;")
#define CPA_WAIT3()  asm volatile("cp.async.wait_group 3;")
#define CPA_WAIT2()  asm volatile("cp.async.wait_group 2;")
#define CPA_WAIT0()  asm volatile("cp.async.wait_group 0;")

// pack 8 floats -> hi uint4 + lo uint4 (value-identical to scalar version)
__device__ __forceinline__ void split8(const float4 a, const float4 b,
                                       uint4& hu, uint4& lu) {
    __half h[8], l[8];
    const float f[8] = {a.x, a.y, a.z, a.w, b.x, b.y, b.z, b.w};
#pragma unroll
    for (int i = 0; i < 8; i++) {
        h[i] = __float2half_rn(f[i]);
        l[i] = __float2half_rn(f[i] - __half2float(h[i]));
    }
    hu.x = ((unsigned)__half_as_ushort(h[1]) << 16) | __half_as_ushort(h[0]);
    hu.y = ((unsigned)__half_as_ushort(h[3]) << 16) | __half_as_ushort(h[2]);
    hu.z = ((unsigned)__half_as_ushort(h[5]) << 16) | __half_as_ushort(h[4]);
    hu.w = ((unsigned)__half_as_ushort(h[7]) << 16) | __half_as_ushort(h[6]);
    lu.x = ((unsigned)__half_as_ushort(l[1]) << 16) | __half_as_ushort(l[0]);
    lu.y = ((unsigned)__half_as_ushort(l[3]) << 16) | __half_as_ushort(l[2]);
    lu.z = ((unsigned)__half_as_ushort(l[5]) << 16) | __half_as_ushort(l[4]);
    lu.w = ((unsigned)__half_as_ushort(l[7]) << 16) | __half_as_ushort(l[6]);
}
__device__ __forceinline__ uint4 hi8(const float4 a, const float4 b) {
    __half h[8];
    const float f[8] = {a.x, a.y, a.z, a.w, b.x, b.y, b.z, b.w};
#pragma unroll
    for (int i = 0; i < 8; i++) h[i] = __float2half_rn(f[i]);
    uint4 u;
    u.x = ((unsigned)__half_as_ushort(h[1]) << 16) | __half_as_ushort(h[0]);
    u.y = ((unsigned)__half_as_ushort(h[3]) << 16) | __half_as_ushort(h[2]);
    u.z = ((unsigned)__half_as_ushort(h[5]) << 16) | __half_as_ushort(h[4]);
    u.w = ((unsigned)__half_as_ushort(h[7]) << 16) | __half_as_ushort(h[6]);
    return u;
}

// ---------------- conversions (vectorized: 8 elems/thread) -------------------
__global__ void f2h_split_v8(const float* __restrict__ in,
                             __half* __restrict__ hi,
                             __half* __restrict__ lo, int n8) {
    int i = blockIdx.x * blockDim.x + threadIdx.x;
    if (i >= n8) return;
    const float4* p = (const float4*)in + 2 * (size_t)i;
    uint4 hu, lu;
    split8(p[0], p[1], hu, lu);
    ((uint4*)hi)[i] = hu;
    ((uint4*)lo)[i] = lu;
}

// all four weights in one launch: Wq -> hi/lo, Wk/Wv/Wo -> hi only
__global__ void wconv_v8(const float* __restrict__ Wq,
                         const float* __restrict__ Wk,
                         const float* __restrict__ Wv,
                         const float* __restrict__ Wo) {
    const int wn8 = (CC * CC) / 8;
    int i = blockIdx.x * blockDim.x + threadIdx.x;
    if (i >= 4 * wn8) return;
    int w = i / wn8, j = i - w * wn8;
    if (w == 0) {
        const float4* p = (const float4*)Wq + 2 * (size_t)j;
        uint4 hu, lu;
        split8(p[0], p[1], hu, lu);
        ((uint4*)g_Wqh)[j] = hu;
        ((uint4*)g_Wql)[j] = lu;
    } else {
        const float* src = (w == 1) ? Wk : (w == 2) ? Wv : Wo;
        __half* dst = (w == 1) ? g_Wkh : (w == 2) ? g_Wvh : g_Woh;
        const float4* p = (const float4*)src + 2 * (size_t)j;
        ((uint4*)dst)[j] = hi8(p[0], p[1]);
    }
}

// cp[h][p][k] = rel_h[h,k,p/14] + rel_w[h,k,p%14], split hi/lo, padded
__global__ void cp_split_kernel(const float* __restrict__ rel_h,
                                const float* __restrict__ rel_w) {
    int idx = blockIdx.x * blockDim.x + threadIdx.x;
    if (idx >= HH * NN * DD) return;
    int h   = idx / (NN * DD);
    int rem = idx - h * (NN * DD);
    int p   = rem / DD;
    int k   = rem - p * DD;
    float v = rel_h[(h * DD + k) * 14 + (p / 14)]
            + rel_w[(h * DD + k) * 14 + (p % 14)];
    __half hi = __float2half_rn(v);
    size_t o = ((size_t)h * PROWS + p) * PSTR + k;
    g_cph[o] = hi;
    g_cpl[o] = __float2half_rn(v - __half2float(hi));
}

#define AST2 24
#define NSTAGE 4
#define KITERS 49

// ============ 3-term split-fp16 HMMA GEMM: Q projection ======================
// 8 warps (256 thr), warp tile 32x56 — reg-safe shape (128 regs, occ ~25%).
#define STG3 ((128 + 128 + 112 + 112) * AST2)

__global__ __launch_bounds__(256) void hgemm_proj3(
    const __half* __restrict__ Ah, const __half* __restrict__ Al,
    const __half* __restrict__ Wh, const __half* __restrict__ Wl,
    const float* __restrict__ bias)
{
    extern __shared__ __half sm[];
    const int t    = threadIdx.x;
    const int lane = t & 31;
    const int wid  = t >> 5;
    const int wm   = wid & 3;
    const int wn   = wid >> 2;
    const int m0   = blockIdx.y * 128;
    const int n0   = blockIdx.x * 112;

    float acc[2][7][4];
#pragma unroll
    for (int i = 0; i < 2; i++)
#pragma unroll
        for (int j = 0; j < 7; j++)
#pragma unroll
            for (int r = 0; r < 4; r++) acc[i][j][r] = 0.f;

    auto prefetch = [&](int kt) {
        const int k0 = kt * 16;
        __half* st = sm + (kt & (NSTAGE - 1)) * STG3;
        for (int v = t; v < 960; v += 256) {
            const __half* g; __half* s;
            if (v < 512) {
                int part = v >> 8, rem = v & 255;
                int row = rem >> 1, ch = rem & 1;
                g = (part ? Al : Ah) + (size_t)(m0 + row) * CC + k0 + ch * 8;
                s = st + part * (128 * AST2) + row * AST2 + ch * 8;
            } else {
                int v2 = v - 512;
                int part = v2 / 224, rem = v2 % 224;
                int row = rem >> 1, ch = rem & 1;
                g = (part ? Wl : Wh) + (size_t)(n0 + row) * CC + k0 + ch * 8;
                s = st + 256 * AST2 + part * (112 * AST2) + row * AST2 + ch * 8;
            }
            CPA16(s, g);
        }
        CPA_COMMIT();
    };

    prefetch(0); prefetch(1); prefetch(2);

    for (int kt = 0; kt < KITERS; kt++) {
        if (kt + 3 < KITERS) prefetch(kt + 3);
        else CPA_COMMIT();
        CPA_WAIT3();
        __syncthreads();

        __half* st  = sm + (kt & (NSTAGE - 1)) * STG3;
        __half* Ash = st;
        __half* Asl = st + 128 * AST2;
        __half* Bsh = st + 256 * AST2;
        __half* Bsl = st + 256 * AST2 + 112 * AST2;

        unsigned afh[2][4], afl[2][4];
#pragma unroll
        for (int mt = 0; mt < 2; mt++) {
            int arow = wm * 32 + mt * 16 + (lane & 15);
            int acol = (lane >> 4) << 3;
            ldsm_x4(afh[mt], Ash + arow * AST2 + acol);
            ldsm_x4(afl[mt], Asl + arow * AST2 + acol);
        }
        unsigned bfh[7][2], bfl[7][2];
#pragma unroll
        for (int p = 0; p < 3; p++) {
            int brow = wn * 56 + p * 16 + (lane & 7) + ((lane & 16) >> 1);
            int bcol = lane & 8;
            ldsm_x4(&bfh[2 * p][0], Bsh + brow * AST2 + bcol);
            ldsm_x4(&bfl[2 * p][0], Bsl + brow * AST2 + bcol);
        }
        {
            int brow = wn * 56 + 48 + (lane & 7);
            int bcol = lane & 8;
            ldsm_x2(bfh[6], Bsh + brow * AST2 + bcol);
            ldsm_x2(bfl[6], Bsl + brow * AST2 + bcol);
        }
#pragma unroll
        for (int mt = 0; mt < 2; mt++)
#pragma unroll
            for (int nt = 0; nt < 7; nt++)
                mma16816(acc[mt][nt], afh[mt], bfh[nt]);
#pragma unroll
        for (int mt = 0; mt < 2; mt++)
#pragma unroll
            for (int nt = 0; nt < 7; nt++)
                mma16816(acc[mt][nt], afh[mt], bfl[nt]);
#pragma unroll
        for (int mt = 0; mt < 2; mt++)
#pragma unroll
            for (int nt = 0; nt < 7; nt++)
                mma16816(acc[mt][nt], afl[mt], bfh[nt]);
        __syncthreads();
    }

    // epilogue: split to hi/lo, write q + q^T padded attention layouts
    auto put = [&](int row, int col, float f) {
        int b = row / NN, n = row - b * NN;
        int h = col / DD, d = col - h * DD;
        size_t bh = (size_t)b * HH + h;
        size_t o1 = (bh * PROWS + n) * PSTR + d;
        size_t o2 = (bh * PROWS + d) * PSTR + n;
        __half hi = __float2half_rn(f);
        __half lo = __float2half_rn(f - __half2float(hi));
        g_qh[o1]  = hi; g_ql[o1]  = lo;
        g_qth[o2] = hi; g_qtl[o2] = lo;
    };
#pragma unroll
    for (int mt = 0; mt < 2; mt++)
#pragma unroll
        for (int nt = 0; nt < 7; nt++) {
            int row = m0 + wm * 32 + mt * 16 + (lane >> 2);
            int col = n0 + wn * 56 + nt * 8 + (lane & 3) * 2;
            float b0 = bias[col], b1 = bias[col + 1];
            put(row,     col,     acc[mt][nt][0] + b0);
            put(row,     col + 1, acc[mt][nt][1] + b1);
            put(row + 8, col,     acc[mt][nt][2] + b0);
            put(row + 8, col + 1, acc[mt][nt][3] + b1);
        }
}

// ============ 1-term fp16 HMMA GEMM: K / V / O projections ==================
// MODE 0: K -> g_kh[bh][n][d];  MODE 1: V -> g_vth[bh][d][n];  MODE 2: fp32 Y
// CTA 128 thr, 4 warps, warp tile 64x56 (B-reuse win, fits registers).
#define STG1 ((128 + 112) * AST2)

template<int MODE>
__global__ __launch_bounds__(128) void hgemm_proj1(
    const __half* __restrict__ Ah, const __half* __restrict__ Wh,
    const float* __restrict__ bias, float* __restrict__ Y)
{
    extern __shared__ __half sm[];
    const int t    = threadIdx.x;
    const int lane = t & 31;
    const int wid  = t >> 5;
    const int wm   = wid & 1;
    const int wn   = wid >> 1;
    const int m0   = blockIdx.y * 128;
    const int n0   = blockIdx.x * 112;

    float acc[4][7][4];
#pragma unroll
    for (int i = 0; i < 4; i++)
#pragma unroll
        for (int j = 0; j < 7; j++)
#pragma unroll
            for (int r = 0; r < 4; r++) acc[i][j][r] = 0.f;

    auto prefetch = [&](int kt) {
        const int k0 = kt * 16;
        __half* st = sm + (kt & (NSTAGE - 1)) * STG1;
        for (int v = t; v < 480; v += 128) {
            const __half* g; __half* s;
            if (v < 256) {
                int row = v >> 1, ch = v & 1;
                g = Ah + (size_t)(m0 + row) * CC + k0 + ch * 8;
                s = st + row * AST2 + ch * 8;
            } else {
                int v2 = v - 256;
                int row = v2 >> 1, ch = v2 & 1;
                g = Wh + (size_t)(n0 + row) * CC + k0 + ch * 8;
                s = st + 128 * AST2 + row * AST2 + ch * 8;
            }
            CPA16(s, g);
        }
        CPA_COMMIT();
    };

    prefetch(0); prefetch(1); prefetch(2);

    for (int kt = 0; kt < KITERS; kt++) {
        if (kt + 3 < KITERS) prefetch(kt + 3);
        else CPA_COMMIT();
        CPA_WAIT3();
        __syncthreads();

        __half* st  = sm + (kt & (NSTAGE - 1)) * STG1;
        __half* Ash = st;
        __half* Bsh = st + 128 * AST2;

        unsigned afh[4][4];
#pragma unroll
        for (int mt = 0; mt < 4; mt++) {
            int arow = wm * 64 + mt * 16 + (lane & 15);
            int acol = (lane >> 4) << 3;
            ldsm_x4(afh[mt], Ash + arow * AST2 + acol);
        }
        unsigned bfh[7][2];
#pragma unroll
        for (int p = 0; p < 3; p++) {
            int brow = wn * 56 + p * 16 + (lane & 7) + ((lane & 16) >> 1);
            int bcol = lane & 8;
            ldsm_x4(&bfh[2 * p][0], Bsh + brow * AST2 + bcol);
        }
        {
            int brow = wn * 56 + 48 + (lane & 7);
            int bcol = lane & 8;
            ldsm_x2(bfh[6], Bsh + brow * AST2 + bcol);
        }
#pragma unroll
        for (int mt = 0; mt < 4; mt++)
#pragma unroll
            for (int nt = 0; nt < 7; nt++)
                mma16816(acc[mt][nt], afh[mt], bfh[nt]);
        __syncthreads();
    }

    auto put = [&](int row, int col, float f) {
        if (MODE == 2) return;
        int b = row / NN, n = row - b * NN;
        int h = col / DD, d = col - h * DD;
        size_t bh = (size_t)b * HH + h;
        __half hi = __float2half_rn(f);
        if (MODE == 0) g_kh [(bh * PROWS + n) * PSTR + d] = hi;
        else           g_vth[(bh * PROWS + d) * PSTR + n] = hi;
    };
#pragma unroll
    for (int mt = 0; mt < 4; mt++)
#pragma unroll
        for (int nt = 0; nt < 7; nt++) {
            int row = m0 + wm * 64 + mt * 16 + (lane >> 2);
            int col = n0 + wn * 56 + nt * 8 + (lane & 3) * 2;
            float b0 = bias[col], b1 = bias[col + 1];
            if (MODE == 2) {
                float2 v0 = make_float2(acc[mt][nt][0] + b0, acc[mt][nt][1] + b1);
                float2 v1 = make_float2(acc[mt][nt][2] + b0, acc[mt][nt][3] + b1);
                *(float2*)(Y + (size_t)row * CC + col) = v0;
                *(float2*)(Y + (size_t)(row + 8) * CC + col) = v1;
            } else {
                put(row,     col,     acc[mt][nt][0] + b0);
                put(row,     col + 1, acc[mt][nt][1] + b1);
                put(row + 8, col,     acc[mt][nt][2] + b0);
                put(row + 8, col + 1, acc[mt][nt][3] + b1);
            }
        }
}

// ============ FUSED logits + RPE + softmax -> fp16 P ========================
// grid (2, NBH): CTA owns 112 full logit rows. 7 warps, warp = 1 m16 x 25 n8
// (acc 100 regs). 3-stage cp.async. Pass2 B frags phased in 2 halves.
#define LS_ST (624 * AST2)          // stage: A1 112 | A2 112 | B1 200 | B2 200 rows
#define OFF_A1 0
#define OFF_A2 (112 * AST2)
#define OFF_B1 (224 * AST2)
#define OFF_B2 (424 * AST2)

__global__ __launch_bounds__(224) void attn_lsm()
{
    extern __shared__ __half sm[];
    const int t    = threadIdx.x;
    const int lane = t & 31;
    const int wid  = t >> 5;        // 0..6
    const int bh   = blockIdx.y;
    const int h    = bh & (HH - 1);
    const int n0   = blockIdx.x * 112;

    const __half* qh  = g_qh  + (size_t)bh * PROWS * PSTR;
    const __half* kh  = g_kh  + (size_t)bh * PROWS * PSTR;
    const __half* qth = g_qth + (size_t)bh * PROWS * PSTR;
    const __half* qtl = g_qtl + (size_t)bh * PROWS * PSTR;
    const __half* cph = g_cph + (size_t)h * PROWS * PSTR;
    const __half* cpl = g_cpl + (size_t)h * PROWS * PSTR;

    float acc[25][4];
#pragma unroll
    for (int j = 0; j < 25; j++)
#pragma unroll
        for (int r = 0; r < 4; r++) acc[j][r] = 0.f;

    // ---- pass 1: Q@K^T over all 196 cols (pad 200) ----
    auto pf1 = [&](int kt) {
        const int k0 = kt * 16;
        __half* st = sm + (kt % 3) * LS_ST;
        for (int v = t; v < 624; v += 224) {
            if (v < 224) {
                int row = v >> 1, ch = v & 1;
                CPA16(st + OFF_A1 + row * AST2 + ch * 8,
                      qh + (size_t)(n0 + row) * PSTR + k0 + ch * 8);
            } else {
                int v2 = v - 224;
                int row = v2 >> 1, ch = v2 & 1;
                CPA16(st + OFF_B1 + row * AST2 + ch * 8,
                      kh + (size_t)row * PSTR + k0 + ch * 8);
            }
        }
        CPA_COMMIT();
    };
    pf1(0); pf1(1);
    for (int kt = 0; kt < 13; kt++) {
        if (kt + 2 < 13) pf1(kt + 2);
        else CPA_COMMIT();
        CPA_WAIT2();
        __syncthreads();
        __half* st = sm + (kt % 3) * LS_ST;
        unsigned af[4];
        ldsm_x4(af, st + OFF_A1 + (wid * 16 + (lane & 15)) * AST2 + ((lane >> 4) << 3));
        unsigned bf[25][2];
#pragma unroll
        for (int p = 0; p < 12; p++) {
            int brow = p * 16 + (lane & 7) + ((lane & 16) >> 1);
            ldsm_x4(&bf[2 * p][0], st + OFF_B1 + brow * AST2 + (lane & 8));
        }
        ldsm_x2(bf[24], st + OFF_B1 + (192 + (lane & 7)) * AST2 + (lane & 8));
#pragma unroll
        for (int nt = 0; nt < 25; nt++) mma16816(acc[nt], af, bf[nt]);
        __syncthreads();
    }
    CPA_WAIT0();
    __syncthreads();

#pragma unroll
    for (int j = 0; j < 25; j++)
#pragma unroll
        for (int r = 0; r < 4; r++) acc[j][r] *= (1.0f / 14.0f);

    // ---- pass 2: cp@Q, 3-term, B phased in 2 halves ----
    auto pf2 = [&](int kt) {
        const int k0 = kt * 16;
        __half* st = sm + (kt % 3) * LS_ST;
        for (int v = t; v < 1248; v += 224) {
            if (v < 224) {
                int row = v >> 1, ch = v & 1;
                CPA16(st + OFF_A1 + row * AST2 + ch * 8,
                      cph + (size_t)(n0 + row) * PSTR + k0 + ch * 8);
            } else if (v < 448) {
                int v2 = v - 224;
                int row = v2 >> 1, ch = v2 & 1;
                CPA16(st + OFF_A2 + row * AST2 + ch * 8,
                      cpl + (size_t)(n0 + row) * PSTR + k0 + ch * 8);
            } else if (v < 848) {
                int v2 = v - 448;
                int row = v2 >> 1, ch = v2 & 1;
                CPA16(st + OFF_B1 + row * AST2 + ch * 8,
                      qth + (size_t)row * PSTR + k0 + ch * 8);
            } else {
                int v2 = v - 848;
                int row = v2 >> 1, ch = v2 & 1;
                CPA16(st + OFF_B2 + row * AST2 + ch * 8,
                      qtl + (size_t)row * PSTR + k0 + ch * 8);
            }
        }
        CPA_COMMIT();
    };
    pf2(0); pf2(1);
    for (int kt = 0; kt < 13; kt++) {
        if (kt + 2 < 13) pf2(kt + 2);
        else CPA_COMMIT();
        CPA_WAIT2();
        __syncthreads();
        __half* st = sm + (kt % 3) * LS_ST;
        unsigned afh[4], afl[4];
        int arow = wid * 16 + (lane & 15);
        int acol = (lane >> 4) << 3;
        ldsm_x4(afh, st + OFF_A1 + arow * AST2 + acol);
        ldsm_x4(afl, st + OFF_A2 + arow * AST2 + acol);
        // half 1: tiles 0..11
        {
            unsigned bfh[12][2], bfl[12][2];
#pragma unroll
            for (int p = 0; p < 6; p++) {
                int brow = p * 16 + (lane & 7) + ((lane & 16) >> 1);
                ldsm_x4(&bfh[2 * p][0], st + OFF_B1 + brow * AST2 + (lane & 8));
                ldsm_x4(&bfl[2 * p][0], st + OFF_B2 + brow * AST2 + (lane & 8));
            }
#pragma unroll
            for (int nt = 0; nt < 12; nt++) mma16816(acc[nt], afh, bfh[nt]);
#pragma unroll
            for (int nt = 0; nt < 12; nt++) mma16816(acc[nt], afl, bfh[nt]);
#pragma unroll
            for (int nt = 0; nt < 12; nt++) mma16816(acc[nt], afh, bfl[nt]);
        }
        // half 2: tiles 12..24
        {
            unsigned bfh[13][2], bfl[13][2];
#pragma unroll
            for (int p = 0; p < 6; p++) {
                int brow = 96 + p * 16 + (lane & 7) + ((lane & 16) >> 1);
                ldsm_x4(&bfh[2 * p][0], st + OFF_B1 + brow * AST2 + (lane & 8));
                ldsm_x4(&bfl[2 * p][0], st + OFF_B2 + brow * AST2 + (lane & 8));
            }
            ldsm_x2(bfh[12], st + OFF_B1 + (192 + (lane & 7)) * AST2 + (lane & 8));
            ldsm_x2(bfl[12], st + OFF_B2 + (192 + (lane & 7)) * AST2 + (lane & 8));
#pragma unroll
            for (int nt = 0; nt < 13; nt++) mma16816(acc[12 + nt], afh, bfh[nt]);
#pragma unroll
            for (int nt = 0; nt < 13; nt++) mma16816(acc[12 + nt], afl, bfh[nt]);
#pragma unroll
            for (int nt = 0; nt < 13; nt++) mma16816(acc[12 + nt], afh, bfl[nt]);
        }
        __syncthreads();
    }

    // ---- epilogue: softmax per row in-register -> fp16 P ----
#pragma unroll
    for (int hf = 0; hf < 2; hf++) {
        int lr = n0 + wid * 16 + (lane >> 2) + hf * 8;
        const int c0 = hf * 2;
        float mx = -1e30f;
#pragma unroll
        for (int nt = 0; nt < 25; nt++) {
            int col = nt * 8 + (lane & 3) * 2;
            if (col >= NN)     { acc[nt][c0] = -1e30f; acc[nt][c0 + 1] = -1e30f; }
            else if (col + 1 >= NN) { acc[nt][c0 + 1] = -1e30f; }
            mx = fmaxf(mx, fmaxf(acc[nt][c0], acc[nt][c0 + 1]));
        }
        mx = fmaxf(mx, __shfl_xor_sync(0xffffffffu, mx, 1));
        mx = fmaxf(mx, __shfl_xor_sync(0xffffffffu, mx, 2));
        float sum = 0.f;
#pragma unroll
        for (int nt = 0; nt < 25; nt++) {
            float e0 = __expf(acc[nt][c0]     - mx);
            float e1 = __expf(acc[nt][c0 + 1] - mx);
            acc[nt][c0] = e0; acc[nt][c0 + 1] = e1;
            sum += e0 + e1;
        }
        sum += __shfl_xor_sync(0xffffffffu, sum, 1);
        sum += __shfl_xor_sync(0xffffffffu, sum, 2);
        float inv = 1.0f / sum;
        if (lr < NN) {
            __half* po = g_ph + ((size_t)bh * PROWS + lr) * PSTR;
#pragma unroll
            for (int nt = 0; nt < 25; nt++) {
                int col = nt * 8 + (lane & 3) * 2;
                if (col < NN)
                    *(__half2*)(po + col) =
                        __floats2half2_rn(acc[nt][c0] * inv, acc[nt][c0 + 1] * inv);
            }
        }
    }
}

// ============ HMMA P@V -> fp16 O (B,N,C) ====================================
#define TST (112 * AST2)
#define VSTG (2 * TST)

__global__ __launch_bounds__(224) void attn_pv_mma()
{
    extern __shared__ __half sm[];
    const int t    = threadIdx.x;
    const int lane = t & 31;
    const int wid  = t >> 5;
    const int bh   = blockIdx.z;
    const int b    = bh >> 2, h = bh & 3;
    const int n0   = blockIdx.y * 112;
    const int c0   = blockIdx.x * 112;

    const __half* ph  = g_ph  + (size_t)bh * PROWS * PSTR;
    const __half* vth = g_vth + (size_t)bh * PROWS * PSTR;

    float acc[14][4];
#pragma unroll
    for (int j = 0; j < 14; j++)
#pragma unroll
        for (int r = 0; r < 4; r++) acc[j][r] = 0.f;

    auto pf = [&](int kt) {
        const int k0 = kt * 16;
        __half* st = sm + (kt & 3) * VSTG;
        for (int v = t; v < 448; v += 224) {
            int tile = v / 224, rem = v - tile * 224;
            int row = rem >> 1, ch = rem & 1;
            const __half* g = (tile ? vth + (size_t)(c0 + row) * PSTR
                                    : ph + (size_t)(n0 + row) * PSTR) + k0 + ch * 8;
            CPA16(st + tile * TST + row * AST2 + ch * 8, g);
        }
        CPA_COMMIT();
    };
    pf(0); pf(1); pf(2);
    for (int kt = 0; kt < 13; kt++) {
        if (kt + 3 < 13) pf(kt + 3);
        else CPA_COMMIT();
        CPA_WAIT3();
        __syncthreads();
        __half* st = sm + (kt & 3) * VSTG;
        unsigned af[4];
        ldsm_x4(af, st + (wid * 16 + (lane & 15)) * AST2 + ((lane >> 4) << 3));
        unsigned bf[14][2];
#pragma unroll
        for (int p = 0; p < 7; p++) {
            int brow = p * 16 + (lane & 7) + ((lane & 16) >> 1);
            ldsm_x4(&bf[2 * p][0], st + TST + brow * AST2 + (lane & 8));
        }
#pragma unroll
        for (int nt = 0; nt < 14; nt++) mma16816(acc[nt], af, bf[nt]);
        __syncthreads();
    }

    // epilogue -> g_Oh[(b*196+n)][h*196+c], fp16
#pragma unroll
    for (int nt = 0; nt < 14; nt++) {
        int n = n0 + wid * 16 + (lane >> 2);
        int c = c0 + nt * 8 + (lane & 3) * 2;
        if (c < NN) {
            size_t colo = (size_t)h * DD + c;
            if (n < NN) {
                size_t ro = ((size_t)b * NN + n) * CC + colo;
                g_Oh[ro]     = __float2half_rn(acc[nt][0]);
                g_Oh[ro + 1] = __float2half_rn(acc[nt][1]);
            }
            if (n + 8 < NN) {
                size_t ro = ((size_t)b * NN + n + 8) * CC + colo;
                g_Oh[ro]     = __float2half_rn(acc[nt][2]);
                g_Oh[ro + 1] = __float2half_rn(acc[nt][3]);
            }
        }
    }
}

// ---------------- launcher --------------------------------------------------
extern "C" void kernel_launch(void* const* d_in, const int* in_sizes, int n_in,
                              void* d_out, int out_size)
{
    const float* x     = (const float*)d_in[0];
    const float* Wq    = (const float*)d_in[1];
    const float* bq    = (const float*)d_in[2];
    const float* Wk    = (const float*)d_in[3];
    const float* bk    = (const float*)d_in[4];
    const float* Wv    = (const float*)d_in[5];
    const float* bv    = (const float*)d_in[6];
    const float* Wo    = (const float*)d_in[7];
    const float* bo    = (const float*)d_in[8];
    const float* rel_h = (const float*)d_in[9];
    const float* rel_w = (const float*)d_in[10];
    float* out = (float*)d_out;

    __half *pXh, *pXl, *pOh, *pWqh, *pWql, *pWkh, *pWvh, *pWoh;
    cudaGetSymbolAddress((void**)&pXh,  g_Xh);
    cudaGetSymbolAddress((void**)&pXl,  g_Xl);
    cudaGetSymbolAddress((void**)&pOh,  g_Oh);
    cudaGetSymbolAddress((void**)&pWqh, g_Wqh);
    cudaGetSymbolAddress((void**)&pWql, g_Wql);
    cudaGetSymbolAddress((void**)&pWkh, g_Wkh);
    cudaGetSymbolAddress((void**)&pWvh, g_Wvh);
    cudaGetSymbolAddress((void**)&pWoh, g_Woh);

    const unsigned smem3  = NSTAGE * STG3 * sizeof(__half);   // 92160
    const unsigned smem1  = NSTAGE * STG1 * sizeof(__half);   // 46080
    const unsigned smemLS = 3 * LS_ST * sizeof(__half);       // 89856
    const unsigned smemV  = 4 * VSTG * sizeof(__half);        // 43008
    cudaFuncSetAttribute(hgemm_proj3,
        cudaFuncAttributeMaxDynamicSharedMemorySize, smem3);
    cudaFuncSetAttribute(hgemm_proj1<0>,
        cudaFuncAttributeMaxDynamicSharedMemorySize, smem1);
    cudaFuncSetAttribute(hgemm_proj1<1>,
        cudaFuncAttributeMaxDynamicSharedMemorySize, smem1);
    cudaFuncSetAttribute(hgemm_proj1<2>,
        cudaFuncAttributeMaxDynamicSharedMemorySize, smem1);
    cudaFuncSetAttribute(attn_lsm,
        cudaFuncAttributeMaxDynamicSharedMemorySize, smemLS);
    cudaFuncSetAttribute(attn_pv_mma,
        cudaFuncAttributeMaxDynamicSharedMemorySize, smemV);

    const int xn8 = (MM * CC) / 8;
    const int wn8 = (CC * CC) / 8;
    // vectorized conversions (8 elems/thread, full-sector stores)
    f2h_split_v8<<<(xn8 + 255) / 256, 256>>>(x, pXh, pXl, xn8);        // 1
    wconv_v8<<<(4 * wn8 + 255) / 256, 256>>>(Wq, Wk, Wv, Wo);          // 2
    cp_split_kernel<<<(HH * NN * DD + 255) / 256, 256>>>(rel_h, rel_w);// 3

    dim3 pgrid(CC / 112, MM / 128);   // (7, 392)
    hgemm_proj3<<<pgrid, 256, smem3>>>(pXh, pXl, pWqh, pWql, bq);      // 4
    hgemm_proj1<0><<<pgrid, 128, smem1>>>(pXh, pWkh, bk, nullptr);     // 5
    hgemm_proj1<1><<<pgrid, 128, smem1>>>(pXh, pWvh, bv, nullptr);     // 6 <- profiled

    attn_lsm<<<dim3(2, NBH), 224, smemLS>>>();
    attn_pv_mma<<<dim3(2, 2, NBH), 224, smemV>>>();

    hgemm_proj1<2><<<pgrid, 128, smem1>>>(pOh, pWoh, bo, out);
}